// round 3
// baseline (speedup 1.0000x reference)
#include <cuda_runtime.h>

#define FIN 128
#define H1  64
#define H2  32
#define MAXN 100000
#define MAXE 1600000

// ---------------- device scratch (no allocations allowed) ----------------
__device__ float g_deg[MAXN];
__device__ float g_dinv[MAXN];
__device__ float g_invdeg[MAXN];
__device__ float g_xw1[MAXN * H1];
__device__ float g_agg1[MAXN * H1];
__device__ float g_xw2[MAXN * H2];
__device__ float g_agg2[MAXN * H2];
__device__ float g_sum1[H1], g_sq1[H1], g_scale1[H1], g_shift1[H1];
__device__ float g_sum2[H2], g_sq2[H2], g_scale2[H2], g_shift2[H2];
__device__ int   g_idx64;

// ---------------- helpers ----------------
__device__ __forceinline__ int load_src(const void* ei, int e, int i) {
    return g_idx64 ? (int)((const long long*)ei)[i] : ((const int*)ei)[i];
}
__device__ __forceinline__ int load_dst(const void* ei, int e, int i) {
    return g_idx64 ? (int)((const long long*)ei)[e + i] : ((const int*)ei)[e + i];
}

// ---------------- kernels ----------------

// Detect whether edge_index is int64 or int32 (deterministic, data-driven).
__global__ void k_detect(const void* ei, int n, int e) {
    if (threadIdx.x == 0 && blockIdx.x == 0) {
        const long long* p = (const long long*)ei;
        int m = e < 512 ? e : 512;
        int ok = 1;
        for (int i = 0; i < m; i++) {
            unsigned long long v = (unsigned long long)p[i];
            if (v >= (unsigned long long)n) { ok = 0; break; }
        }
        g_idx64 = ok;
    }
}

__global__ void k_zero(int n) {
    int i = blockIdx.x * blockDim.x + threadIdx.x;
    if (i < n) g_deg[i] = 0.f;
    if (i < H1) { g_sum1[i] = 0.f; g_sq1[i] = 0.f; }
    if (i < H2) { g_sum2[i] = 0.f; g_sq2[i] = 0.f; }
}

__global__ void k_deg(const void* ei, const float* __restrict__ ew, int e) {
    int i = blockIdx.x * blockDim.x + threadIdx.x;
    if (i >= e) return;
    int d = load_dst(ei, e, i);
    atomicAdd(&g_deg[d], ew[i]);
}

__global__ void k_degfin(int n) {
    int i = blockIdx.x * blockDim.x + threadIdx.x;
    if (i >= n) return;
    float d = g_deg[i] + 1.0f;
    g_dinv[i]   = rsqrtf(d);
    g_invdeg[i] = 1.0f / d;
}

// xw1 = x @ W1 ; agg1 = xw1 * invdeg (self-loop term).  Row-per-thread.
__global__ __launch_bounds__(256) void k_gemm1(const float* __restrict__ x,
                                               const float* __restrict__ W1, int n) {
    __shared__ float ws[FIN * H1];  // 32 KB
    int tid = threadIdx.x;
    for (int i = tid; i < FIN * H1 / 4; i += blockDim.x)
        ((float4*)ws)[i] = ((const float4*)W1)[i];
    __syncthreads();

    int row = blockIdx.x * blockDim.x + tid;
    if (row >= n) return;

    float acc[H1];
#pragma unroll
    for (int c = 0; c < H1; c++) acc[c] = 0.f;

    const float4* xr = (const float4*)(x + (long)row * FIN);
#pragma unroll 1
    for (int kb = 0; kb < FIN / 4; kb++) {
        float4 xv = xr[kb];
        const float* w0 = ws + (kb * 4) * H1;
#pragma unroll
        for (int c = 0; c < H1; c++) {
            acc[c] += xv.x * w0[c] + xv.y * w0[H1 + c]
                    + xv.z * w0[2 * H1 + c] + xv.w * w0[3 * H1 + c];
        }
    }
    float inv = g_invdeg[row];
    long base = (long)row * H1;
#pragma unroll
    for (int c = 0; c < H1; c++) {
        g_xw1[base + c]  = acc[c];
        g_agg1[base + c] = acc[c] * inv;
    }
}

// agg1[dst] += xw1[src] * (dinv[src]*ew*dinv[dst]);  warp per edge, 64 features.
__global__ void k_scatter1(const void* ei, const float* __restrict__ ew, int e) {
    int gt   = blockIdx.x * blockDim.x + threadIdx.x;
    int w    = gt >> 5;
    int lane = gt & 31;
    if (w >= e) return;
    int s = load_src(ei, e, w);
    int d = load_dst(ei, e, w);
    float nrm = g_dinv[s] * ew[w] * g_dinv[d];
    const float* xs = g_xw1 + (long)s * H1;
    float* ad = g_agg1 + (long)d * H1;
    atomicAdd(&ad[lane],      xs[lane]      * nrm);
    atomicAdd(&ad[lane + 32], xs[lane + 32] * nrm);
}

// Column sum / sum-of-squares for BN (bias cancels under mean subtraction).
template <int H>
__global__ void k_bnstats(const float* __restrict__ a, float* __restrict__ sum,
                          float* __restrict__ sq, int n) {
    __shared__ float ss[256], qq[256];
    int tid = threadIdx.x;
    int col = tid % H;
    int stripe = tid / H;
    const int NS = 256 / H;
    float s = 0.f, q = 0.f;
    for (int r = blockIdx.x * NS + stripe; r < n; r += gridDim.x * NS) {
        float v = a[(long)r * H + col];
        s += v;
        q += v * v;
    }
    ss[tid] = s; qq[tid] = q;
    __syncthreads();
    if (stripe == 0) {
#pragma unroll
        for (int k = 1; k < NS; k++) { s += ss[col + k * H]; q += qq[col + k * H]; }
        atomicAdd(&sum[col], s);
        atomicAdd(&sq[col],  q);
    }
}

template <int H>
__global__ void k_bnfin(const float* __restrict__ sum, const float* __restrict__ sq,
                        const float* __restrict__ g, const float* __restrict__ be,
                        float* __restrict__ scale, float* __restrict__ shift, int n) {
    int i = threadIdx.x;
    if (i < H) {
        float m = sum[i] / (float)n;
        float v = sq[i] / (float)n - m * m;
        float s = g[i] * rsqrtf(v + 1e-5f);
        scale[i] = s;
        shift[i] = be[i] - m * s;
    }
}

// h1n = relu(bn1(agg1)); xw2 = h1n @ W2; agg2 = xw2*invdeg.  Row-per-thread.
__global__ __launch_bounds__(256) void k_gemm2(const float* __restrict__ W2, int n) {
    __shared__ float ws[H1 * H2];  // 8 KB
    __shared__ float s1[H1], t1[H1];
    int tid = threadIdx.x;
    for (int i = tid; i < H1 * H2; i += blockDim.x) ws[i] = W2[i];
    if (tid < H1) { s1[tid] = g_scale1[tid]; t1[tid] = g_shift1[tid]; }
    __syncthreads();

    int row = blockIdx.x * blockDim.x + tid;
    if (row >= n) return;

    float acc[H2];
#pragma unroll
    for (int c = 0; c < H2; c++) acc[c] = 0.f;

    const float4* ar = (const float4*)(g_agg1 + (long)row * H1);
#pragma unroll 1
    for (int kb = 0; kb < H1 / 4; kb++) {
        float4 av = ar[kb];
        float vv[4] = {av.x, av.y, av.z, av.w};
#pragma unroll
        for (int u = 0; u < 4; u++) {
            int k = kb * 4 + u;
            float v = fmaxf(vv[u] * s1[k] + t1[k], 0.f);
            const float* w = ws + k * H2;
#pragma unroll
            for (int c = 0; c < H2; c++) acc[c] += v * w[c];
        }
    }
    float inv = g_invdeg[row];
    long base = (long)row * H2;
#pragma unroll
    for (int c = 0; c < H2; c++) {
        g_xw2[base + c]  = acc[c];
        g_agg2[base + c] = acc[c] * inv;
    }
}

// agg2[dst] += xw2[src]*norm; warp per edge, 32 features.
__global__ void k_scatter2(const void* ei, const float* __restrict__ ew, int e) {
    int gt   = blockIdx.x * blockDim.x + threadIdx.x;
    int w    = gt >> 5;
    int lane = gt & 31;
    if (w >= e) return;
    int s = load_src(ei, e, w);
    int d = load_dst(ei, e, w);
    float nrm = g_dinv[s] * ew[w] * g_dinv[d];
    atomicAdd(&g_agg2[(long)d * H2 + lane], g_xw2[(long)s * H2 + lane] * nrm);
}

// out[row] = relu(bn2(agg2[row])) . Wl + bl   (warp per row)
__global__ void k_final(const float* __restrict__ Wl, const float* __restrict__ bl,
                        float* __restrict__ out, int n) {
    int gt   = blockIdx.x * blockDim.x + threadIdx.x;
    int row  = gt >> 5;
    int lane = gt & 31;
    if (row >= n) return;
    float v = g_agg2[(long)row * H2 + lane];
    v = fmaxf(v * g_scale2[lane] + g_shift2[lane], 0.f) * Wl[lane];
#pragma unroll
    for (int off = 16; off > 0; off >>= 1)
        v += __shfl_xor_sync(0xFFFFFFFFu, v, off);
    if (lane == 0) out[row] = v + bl[0];
}

// ---------------- launch ----------------
extern "C" void kernel_launch(void* const* d_in, const int* in_sizes, int n_in,
                              void* d_out, int out_size) {
    const float* x  = (const float*)d_in[0];
    const void*  ei = d_in[1];
    const float* ew = (const float*)d_in[2];
    const float* W1 = (const float*)d_in[3];
    const float* g1 = (const float*)d_in[5];
    const float* be1= (const float*)d_in[6];
    const float* W2 = (const float*)d_in[7];
    const float* g2 = (const float*)d_in[9];
    const float* be2= (const float*)d_in[10];
    const float* Wl = (const float*)d_in[11];
    const float* bl = (const float*)d_in[12];
    float* out = (float*)d_out;

    int n = in_sizes[0] / FIN;   // 100000
    int e = in_sizes[2];         // 1600000

    float *p_sum1, *p_sq1, *p_sc1, *p_sh1, *p_sum2, *p_sq2, *p_sc2, *p_sh2, *p_agg1, *p_agg2;
    cudaGetSymbolAddress((void**)&p_sum1, g_sum1);
    cudaGetSymbolAddress((void**)&p_sq1,  g_sq1);
    cudaGetSymbolAddress((void**)&p_sc1,  g_scale1);
    cudaGetSymbolAddress((void**)&p_sh1,  g_shift1);
    cudaGetSymbolAddress((void**)&p_sum2, g_sum2);
    cudaGetSymbolAddress((void**)&p_sq2,  g_sq2);
    cudaGetSymbolAddress((void**)&p_sc2,  g_scale2);
    cudaGetSymbolAddress((void**)&p_sh2,  g_shift2);
    cudaGetSymbolAddress((void**)&p_agg1, g_agg1);
    cudaGetSymbolAddress((void**)&p_agg2, g_agg2);

    int tb = 256;
    int gN  = (n + tb - 1) / tb;
    int gE  = (e + tb - 1) / tb;
    int gEw = (e * 32 + tb - 1) / tb;     // warp per edge
    int gNw = (n * 32 + tb - 1) / tb;     // warp per row

    k_detect<<<1, 32>>>(ei, n, e);
    k_zero<<<gN, tb>>>(n);
    k_deg<<<gE, tb>>>(ei, ew, e);
    k_degfin<<<gN, tb>>>(n);

    k_gemm1<<<gN, tb>>>(x, W1, n);
    k_scatter1<<<gEw, tb>>>(ei, ew, e);

    k_bnstats<H1><<<512, tb>>>(p_agg1, p_sum1, p_sq1, n);
    k_bnfin<H1><<<1, H1>>>(p_sum1, p_sq1, g1, be1, p_sc1, p_sh1, n);

    k_gemm2<<<gN, tb>>>(W2, n);
    k_scatter2<<<gEw, tb>>>(ei, ew, e);

    k_bnstats<H2><<<512, tb>>>(p_agg2, p_sum2, p_sq2, n);
    k_bnfin<H2><<<1, H2>>>(p_sum2, p_sq2, g2, be2, p_sc2, p_sh2, n);

    k_final<<<gNw, tb>>>(Wl, bl, out, n);
}

// round 4
// speedup vs baseline: 1.4316x; 1.4316x over previous
#include <cuda_runtime.h>

#define FIN 128
#define H1  64
#define H2  32
#define MAXN 100000
#define MAXE 1600000

// ---------------- device scratch (no allocations allowed) ----------------
__device__ float g_deg[MAXN];
__device__ float g_dinv[MAXN];
__device__ float g_invdeg[MAXN];
__device__ float g_xw1[MAXN * H1];
__device__ float g_agg1[MAXN * H1];
__device__ float g_xw2[MAXN * H2];
__device__ float g_agg2[MAXN * H2];
__device__ float g_sum1[H1], g_sq1[H1], g_scale1[H1], g_shift1[H1];
__device__ float g_sum2[H2], g_sq2[H2], g_scale2[H2], g_shift2[H2];
__device__ int   g_idx64;

// ---------------- helpers ----------------
__device__ __forceinline__ int load_src(const void* ei, int e, int i) {
    return g_idx64 ? (int)((const long long*)ei)[i] : ((const int*)ei)[i];
}
__device__ __forceinline__ int load_dst(const void* ei, int e, int i) {
    return g_idx64 ? (int)((const long long*)ei)[e + i] : ((const int*)ei)[e + i];
}

// Vectorized fire-and-forget atomic add (sm_90+): 1 instruction, 16 bytes.
__device__ __forceinline__ void red_add_v4(float4* addr, float a, float b, float c, float d) {
    asm volatile("red.global.add.v4.f32 [%0], {%1, %2, %3, %4};"
                 :: "l"(addr), "f"(a), "f"(b), "f"(c), "f"(d) : "memory");
}

// ---------------- kernels ----------------

// Detect whether edge_index is int64 or int32 (deterministic, data-driven).
__global__ void k_detect(const void* ei, int n, int e) {
    if (threadIdx.x == 0 && blockIdx.x == 0) {
        const long long* p = (const long long*)ei;
        int m = e < 512 ? e : 512;
        int ok = 1;
        for (int i = 0; i < m; i++) {
            unsigned long long v = (unsigned long long)p[i];
            if (v >= (unsigned long long)n) { ok = 0; break; }
        }
        g_idx64 = ok;
    }
}

__global__ void k_zero(int n) {
    int i = blockIdx.x * blockDim.x + threadIdx.x;
    if (i < n) g_deg[i] = 0.f;
    if (i < H1) { g_sum1[i] = 0.f; g_sq1[i] = 0.f; }
    if (i < H2) { g_sum2[i] = 0.f; g_sq2[i] = 0.f; }
}

__global__ void k_deg(const void* ei, const float* __restrict__ ew, int e) {
    int i = blockIdx.x * blockDim.x + threadIdx.x;
    if (i >= e) return;
    int d = load_dst(ei, e, i);
    atomicAdd(&g_deg[d], ew[i]);
}

__global__ void k_degfin(int n) {
    int i = blockIdx.x * blockDim.x + threadIdx.x;
    if (i >= n) return;
    float d = g_deg[i] + 1.0f;
    g_dinv[i]   = rsqrtf(d);
    g_invdeg[i] = 1.0f / d;
}

// xw1 = x @ W1 ; agg1 = xw1 * invdeg (self-loop term).  Row-per-thread,
// weights fetched as float4 shared loads (LDS.128) to cut issue pressure.
__global__ __launch_bounds__(256) void k_gemm1(const float* __restrict__ x,
                                               const float* __restrict__ W1, int n) {
    __shared__ float ws[FIN * H1];  // 32 KB
    int tid = threadIdx.x;
    for (int i = tid; i < FIN * H1 / 4; i += blockDim.x)
        ((float4*)ws)[i] = ((const float4*)W1)[i];
    __syncthreads();

    int row = blockIdx.x * blockDim.x + tid;
    if (row >= n) return;

    float acc[H1];
#pragma unroll
    for (int c = 0; c < H1; c++) acc[c] = 0.f;

    const float4* xr = (const float4*)(x + (long)row * FIN);
#pragma unroll 1
    for (int kb = 0; kb < FIN / 4; kb++) {
        float4 xv = xr[kb];
        const float4* w0 = (const float4*)(ws + (kb * 4 + 0) * H1);
        const float4* w1 = (const float4*)(ws + (kb * 4 + 1) * H1);
        const float4* w2 = (const float4*)(ws + (kb * 4 + 2) * H1);
        const float4* w3 = (const float4*)(ws + (kb * 4 + 3) * H1);
#pragma unroll
        for (int cq = 0; cq < H1 / 4; cq++) {
            float4 a0 = w0[cq], a1 = w1[cq], a2 = w2[cq], a3 = w3[cq];
            acc[cq * 4 + 0] += xv.x * a0.x + xv.y * a1.x + xv.z * a2.x + xv.w * a3.x;
            acc[cq * 4 + 1] += xv.x * a0.y + xv.y * a1.y + xv.z * a2.y + xv.w * a3.y;
            acc[cq * 4 + 2] += xv.x * a0.z + xv.y * a1.z + xv.z * a2.z + xv.w * a3.z;
            acc[cq * 4 + 3] += xv.x * a0.w + xv.y * a1.w + xv.z * a2.w + xv.w * a3.w;
        }
    }
    float inv = g_invdeg[row];
    long base = (long)row * H1;
#pragma unroll
    for (int c = 0; c < H1; c++) {
        g_xw1[base + c]  = acc[c];
        g_agg1[base + c] = acc[c] * inv;
    }
}

// agg1[dst] += xw1[src] * norm.  8 threads/edge, 2 x red.v4 each (64 floats).
__global__ void k_scatter1(const void* ei, const float* __restrict__ ew, int e) {
    int gt   = blockIdx.x * blockDim.x + threadIdx.x;
    int eidx = gt >> 3;          // 8 threads per edge
    int sub  = gt & 7;
    if (eidx >= e) return;

    int lane = threadIdx.x & 31;
    int base_lane = lane & ~7;   // leader lane of this 8-thread group

    int s = 0, d = 0; float nrm = 0.f;
    if (sub == 0) {
        s = load_src(ei, e, eidx);
        d = load_dst(ei, e, eidx);
        nrm = g_dinv[s] * ew[eidx] * g_dinv[d];
    }
    s   = __shfl_sync(0xFFFFFFFFu, s,   base_lane);
    d   = __shfl_sync(0xFFFFFFFFu, d,   base_lane);
    nrm = __shfl_sync(0xFFFFFFFFu, nrm, base_lane);

    const float4* xs = (const float4*)(g_xw1 + (long)s * H1) + sub * 2;
    float4*       ad = (float4*)(g_agg1 + (long)d * H1) + sub * 2;
    float4 v0 = xs[0];
    float4 v1 = xs[1];
    red_add_v4(&ad[0], v0.x * nrm, v0.y * nrm, v0.z * nrm, v0.w * nrm);
    red_add_v4(&ad[1], v1.x * nrm, v1.y * nrm, v1.z * nrm, v1.w * nrm);
}

// Column sum / sum-of-squares for BN (bias cancels under mean subtraction).
template <int H>
__global__ void k_bnstats(const float* __restrict__ a, float* __restrict__ sum,
                          float* __restrict__ sq, int n) {
    __shared__ float ss[256], qq[256];
    int tid = threadIdx.x;
    int col = tid % H;
    int stripe = tid / H;
    const int NS = 256 / H;
    float s = 0.f, q = 0.f;
    for (int r = blockIdx.x * NS + stripe; r < n; r += gridDim.x * NS) {
        float v = a[(long)r * H + col];
        s += v;
        q += v * v;
    }
    ss[tid] = s; qq[tid] = q;
    __syncthreads();
    if (stripe == 0) {
#pragma unroll
        for (int k = 1; k < NS; k++) { s += ss[col + k * H]; q += qq[col + k * H]; }
        atomicAdd(&sum[col], s);
        atomicAdd(&sq[col],  q);
    }
}

template <int H>
__global__ void k_bnfin(const float* __restrict__ sum, const float* __restrict__ sq,
                        const float* __restrict__ g, const float* __restrict__ be,
                        float* __restrict__ scale, float* __restrict__ shift, int n) {
    int i = threadIdx.x;
    if (i < H) {
        float m = sum[i] / (float)n;
        float v = sq[i] / (float)n - m * m;
        float s = g[i] * rsqrtf(v + 1e-5f);
        scale[i] = s;
        shift[i] = be[i] - m * s;
    }
}

// h1n = relu(bn1(agg1)); xw2 = h1n @ W2; agg2 = xw2*invdeg.  Row-per-thread.
__global__ __launch_bounds__(256) void k_gemm2(const float* __restrict__ W2, int n) {
    __shared__ float ws[H1 * H2];  // 8 KB
    __shared__ float s1[H1], t1[H1];
    int tid = threadIdx.x;
    for (int i = tid; i < H1 * H2; i += blockDim.x) ws[i] = W2[i];
    if (tid < H1) { s1[tid] = g_scale1[tid]; t1[tid] = g_shift1[tid]; }
    __syncthreads();

    int row = blockIdx.x * blockDim.x + tid;
    if (row >= n) return;

    float acc[H2];
#pragma unroll
    for (int c = 0; c < H2; c++) acc[c] = 0.f;

    const float4* ar = (const float4*)(g_agg1 + (long)row * H1);
#pragma unroll 1
    for (int kb = 0; kb < H1 / 4; kb++) {
        float4 av = ar[kb];
        float vv[4] = {av.x, av.y, av.z, av.w};
#pragma unroll
        for (int u = 0; u < 4; u++) {
            int k = kb * 4 + u;
            float v = fmaxf(vv[u] * s1[k] + t1[k], 0.f);
            const float4* w = (const float4*)(ws + k * H2);
#pragma unroll
            for (int cq = 0; cq < H2 / 4; cq++) {
                float4 a0 = w[cq];
                acc[cq * 4 + 0] += v * a0.x;
                acc[cq * 4 + 1] += v * a0.y;
                acc[cq * 4 + 2] += v * a0.z;
                acc[cq * 4 + 3] += v * a0.w;
            }
        }
    }
    float inv = g_invdeg[row];
    long base = (long)row * H2;
#pragma unroll
    for (int c = 0; c < H2; c++) {
        g_xw2[base + c]  = acc[c];
        g_agg2[base + c] = acc[c] * inv;
    }
}

// agg2[dst] += xw2[src]*norm.  8 threads/edge, 1 x red.v4 each (32 floats).
__global__ void k_scatter2(const void* ei, const float* __restrict__ ew, int e) {
    int gt   = blockIdx.x * blockDim.x + threadIdx.x;
    int eidx = gt >> 3;
    int sub  = gt & 7;
    if (eidx >= e) return;

    int lane = threadIdx.x & 31;
    int base_lane = lane & ~7;

    int s = 0, d = 0; float nrm = 0.f;
    if (sub == 0) {
        s = load_src(ei, e, eidx);
        d = load_dst(ei, e, eidx);
        nrm = g_dinv[s] * ew[eidx] * g_dinv[d];
    }
    s   = __shfl_sync(0xFFFFFFFFu, s,   base_lane);
    d   = __shfl_sync(0xFFFFFFFFu, d,   base_lane);
    nrm = __shfl_sync(0xFFFFFFFFu, nrm, base_lane);

    const float4* xs = (const float4*)(g_xw2 + (long)s * H2) + sub;
    float4*       ad = (float4*)(g_agg2 + (long)d * H2) + sub;
    float4 v0 = xs[0];
    red_add_v4(ad, v0.x * nrm, v0.y * nrm, v0.z * nrm, v0.w * nrm);
}

// out[row] = relu(bn2(agg2[row])) . Wl + bl   (warp per row)
__global__ void k_final(const float* __restrict__ Wl, const float* __restrict__ bl,
                        float* __restrict__ out, int n) {
    int gt   = blockIdx.x * blockDim.x + threadIdx.x;
    int row  = gt >> 5;
    int lane = gt & 31;
    if (row >= n) return;
    float v = g_agg2[(long)row * H2 + lane];
    v = fmaxf(v * g_scale2[lane] + g_shift2[lane], 0.f) * Wl[lane];
#pragma unroll
    for (int off = 16; off > 0; off >>= 1)
        v += __shfl_xor_sync(0xFFFFFFFFu, v, off);
    if (lane == 0) out[row] = v + bl[0];
}

// ---------------- launch ----------------
extern "C" void kernel_launch(void* const* d_in, const int* in_sizes, int n_in,
                              void* d_out, int out_size) {
    const float* x  = (const float*)d_in[0];
    const void*  ei = d_in[1];
    const float* ew = (const float*)d_in[2];
    const float* W1 = (const float*)d_in[3];
    const float* g1 = (const float*)d_in[5];
    const float* be1= (const float*)d_in[6];
    const float* W2 = (const float*)d_in[7];
    const float* g2 = (const float*)d_in[9];
    const float* be2= (const float*)d_in[10];
    const float* Wl = (const float*)d_in[11];
    const float* bl = (const float*)d_in[12];
    float* out = (float*)d_out;

    int n = in_sizes[0] / FIN;   // 100000
    int e = in_sizes[2];         // 1600000

    float *p_sum1, *p_sq1, *p_sc1, *p_sh1, *p_sum2, *p_sq2, *p_sc2, *p_sh2, *p_agg1, *p_agg2;
    cudaGetSymbolAddress((void**)&p_sum1, g_sum1);
    cudaGetSymbolAddress((void**)&p_sq1,  g_sq1);
    cudaGetSymbolAddress((void**)&p_sc1,  g_scale1);
    cudaGetSymbolAddress((void**)&p_sh1,  g_shift1);
    cudaGetSymbolAddress((void**)&p_sum2, g_sum2);
    cudaGetSymbolAddress((void**)&p_sq2,  g_sq2);
    cudaGetSymbolAddress((void**)&p_sc2,  g_scale2);
    cudaGetSymbolAddress((void**)&p_sh2,  g_shift2);
    cudaGetSymbolAddress((void**)&p_agg1, g_agg1);
    cudaGetSymbolAddress((void**)&p_agg2, g_agg2);

    int tb = 256;
    int gN  = (n + tb - 1) / tb;
    int gE  = (e + tb - 1) / tb;
    int gE8 = (int)(((long)e * 8 + tb - 1) / tb);   // 8 threads per edge
    int gNw = (int)(((long)n * 32 + tb - 1) / tb);  // warp per row

    k_detect<<<1, 32>>>(ei, n, e);
    k_zero<<<gN, tb>>>(n);
    k_deg<<<gE, tb>>>(ei, ew, e);
    k_degfin<<<gN, tb>>>(n);

    k_gemm1<<<gN, tb>>>(x, W1, n);
    k_scatter1<<<gE8, tb>>>(ei, ew, e);

    k_bnstats<H1><<<512, tb>>>(p_agg1, p_sum1, p_sq1, n);
    k_bnfin<H1><<<1, H1>>>(p_sum1, p_sq1, g1, be1, p_sc1, p_sh1, n);

    k_gemm2<<<gN, tb>>>(W2, n);
    k_scatter2<<<gE8, tb>>>(ei, ew, e);

    k_bnstats<H2><<<512, tb>>>(p_agg2, p_sum2, p_sq2, n);
    k_bnfin<H2><<<1, H2>>>(p_sum2, p_sq2, g2, be2, p_sc2, p_sh2, n);

    k_final<<<gNw, tb>>>(Wl, bl, out, n);
}

// round 5
// speedup vs baseline: 1.9896x; 1.3897x over previous
#include <cuda_runtime.h>

#define FIN 128
#define H1  64
#define H2  32
#define MAXN 100000
#define MAXE 1600000
#define SCAN_B 1024

// ---------------- device scratch (no allocations allowed) ----------------
__device__ float g_deg[MAXN];
__device__ float g_dinv[MAXN];
__device__ float g_invdeg[MAXN];
__device__ float g_xw1[MAXN * H1];
__device__ float g_h1[MAXN * H1];     // post-aggregation layer1 (pre-BN)
__device__ float g_xw2[MAXN * H2];
__device__ float g_agg2[MAXN * H2];
__device__ float g_sum1[H1], g_sq1[H1], g_scale1[H1], g_shift1[H1];
__device__ float g_sum2[H2], g_sq2[H2], g_scale2[H2], g_shift2[H2];
__device__ int   g_idx64;
// CSR
__device__ int   g_cnt[MAXN];
__device__ int   g_off[MAXN + 1];
__device__ int   g_cur[MAXN];
__device__ int   g_csrc[MAXE];
__device__ float g_cnorm[MAXE];
__device__ int   g_bsum[128];
__device__ int   g_carry[128];

// ---------------- helpers ----------------
__device__ __forceinline__ int load_src(const void* ei, int e, int i) {
    return g_idx64 ? (int)((const long long*)ei)[i] : ((const int*)ei)[i];
}
__device__ __forceinline__ int load_dst(const void* ei, int e, int i) {
    return g_idx64 ? (int)((const long long*)ei)[e + i] : ((const int*)ei)[e + i];
}

// ---------------- kernels ----------------

// Detect whether edge_index is int64 or int32 (deterministic, data-driven).
__global__ void k_detect(const void* ei, int n, int e) {
    if (threadIdx.x == 0 && blockIdx.x == 0) {
        const long long* p = (const long long*)ei;
        int m = e < 512 ? e : 512;
        int ok = 1;
        for (int i = 0; i < m; i++) {
            unsigned long long v = (unsigned long long)p[i];
            if (v >= (unsigned long long)n) { ok = 0; break; }
        }
        g_idx64 = ok;
    }
}

__global__ void k_zero(int n) {
    int i = blockIdx.x * blockDim.x + threadIdx.x;
    if (i < n) { g_deg[i] = 0.f; g_cnt[i] = 0; }
    if (i < H1) { g_sum1[i] = 0.f; g_sq1[i] = 0.f; }
    if (i < H2) { g_sum2[i] = 0.f; g_sq2[i] = 0.f; }
}

// Weighted in-degree + integer in-degree histogram, one edge pass.
__global__ void k_hist(const void* ei, const float* __restrict__ ew, int e) {
    int i = blockIdx.x * blockDim.x + threadIdx.x;
    if (i >= e) return;
    int d = load_dst(ei, e, i);
    atomicAdd(&g_deg[d], ew[i]);
    atomicAdd(&g_cnt[d], 1);
}

__global__ void k_degfin(int n) {
    int i = blockIdx.x * blockDim.x + threadIdx.x;
    if (i >= n) return;
    float d = g_deg[i] + 1.0f;
    g_dinv[i]   = rsqrtf(d);
    g_invdeg[i] = 1.0f / d;
}

// ---- 3-phase exclusive scan over g_cnt -> g_off ----
__global__ __launch_bounds__(SCAN_B) void k_scan1(int n) {
    __shared__ int sh[SCAN_B];
    int i = blockIdx.x * SCAN_B + threadIdx.x;
    int v = (i < n) ? g_cnt[i] : 0;
    sh[threadIdx.x] = v;
    __syncthreads();
    for (int o = 1; o < SCAN_B; o <<= 1) {
        int t = (threadIdx.x >= o) ? sh[threadIdx.x - o] : 0;
        __syncthreads();
        sh[threadIdx.x] += t;
        __syncthreads();
    }
    if (i < n) g_off[i] = sh[threadIdx.x] - v;   // exclusive
    if (threadIdx.x == SCAN_B - 1) g_bsum[blockIdx.x] = sh[threadIdx.x];
}

__global__ void k_scan2(int nb) {
    __shared__ int sh[128];
    int tid = threadIdx.x;
    sh[tid] = (tid < nb) ? g_bsum[tid] : 0;
    __syncthreads();
    if (tid == 0) {
        int acc = 0;
        for (int b = 0; b < nb; b++) { int t = sh[b]; g_carry[b] = acc; acc += t; }
    }
}

__global__ void k_scan3(int n, int e) {
    int i = blockIdx.x * blockDim.x + threadIdx.x;
    if (i < n) {
        int v = g_off[i] + g_carry[i / SCAN_B];
        g_off[i] = v;
        g_cur[i] = v;
    }
    if (i == 0) g_off[n] = e;
}

// Fill CSR: slot (src, norm) per edge, bucketed by dst.
__global__ void k_fill(const void* ei, const float* __restrict__ ew, int e) {
    int i = blockIdx.x * blockDim.x + threadIdx.x;
    if (i >= e) return;
    int s = load_src(ei, e, i);
    int d = load_dst(ei, e, i);
    int p = atomicAdd(&g_cur[d], 1);
    g_csrc[p]  = s;
    g_cnorm[p] = g_dinv[s] * ew[i] * g_dinv[d];
}

// xw1 = x @ W1.  Row-per-thread, float4 shared weight loads.
__global__ __launch_bounds__(256) void k_gemm1(const float* __restrict__ x,
                                               const float* __restrict__ W1, int n) {
    __shared__ float ws[FIN * H1];  // 32 KB
    int tid = threadIdx.x;
    for (int i = tid; i < FIN * H1 / 4; i += blockDim.x)
        ((float4*)ws)[i] = ((const float4*)W1)[i];
    __syncthreads();

    int row = blockIdx.x * blockDim.x + tid;
    if (row >= n) return;

    float acc[H1];
#pragma unroll
    for (int c = 0; c < H1; c++) acc[c] = 0.f;

    const float4* xr = (const float4*)(x + (long)row * FIN);
#pragma unroll 1
    for (int kb = 0; kb < FIN / 4; kb++) {
        float4 xv = xr[kb];
        const float4* w0 = (const float4*)(ws + (kb * 4 + 0) * H1);
        const float4* w1 = (const float4*)(ws + (kb * 4 + 1) * H1);
        const float4* w2 = (const float4*)(ws + (kb * 4 + 2) * H1);
        const float4* w3 = (const float4*)(ws + (kb * 4 + 3) * H1);
#pragma unroll
        for (int cq = 0; cq < H1 / 4; cq++) {
            float4 a0 = w0[cq], a1 = w1[cq], a2 = w2[cq], a3 = w3[cq];
            acc[cq * 4 + 0] += xv.x * a0.x + xv.y * a1.x + xv.z * a2.x + xv.w * a3.x;
            acc[cq * 4 + 1] += xv.x * a0.y + xv.y * a1.y + xv.z * a2.y + xv.w * a3.y;
            acc[cq * 4 + 2] += xv.x * a0.z + xv.y * a1.z + xv.z * a2.z + xv.w * a3.z;
            acc[cq * 4 + 3] += xv.x * a0.w + xv.y * a1.w + xv.z * a2.w + xv.w * a3.w;
        }
    }
    long base = (long)row * H1;
#pragma unroll
    for (int c = 0; c < H1; c++) g_xw1[base + c] = acc[c];
}

// Gather-aggregate layer1 (warp per node, grid-stride) + fused BN stats.
__global__ __launch_bounds__(256) void k_gather1(int n) {
    __shared__ float s_sum[H1], s_sq[H1];
    int tid  = threadIdx.x;
    int lane = tid & 31;
    if (tid < H1) { s_sum[tid] = 0.f; s_sq[tid] = 0.f; }
    __syncthreads();

    int wglob  = (blockIdx.x * blockDim.x + tid) >> 5;
    int nwarps = (gridDim.x * blockDim.x) >> 5;

    float st0 = 0.f, sq0 = 0.f, st1 = 0.f, sq1 = 0.f;

    for (int d = wglob; d < n; d += nwarps) {
        float inv = g_invdeg[d];
        long  db  = (long)d * H1;
        float a0 = g_xw1[db + lane]      * inv;   // self-loop term
        float a1 = g_xw1[db + lane + 32] * inv;

        int off0 = g_off[d], off1 = g_off[d + 1];
        for (int base = off0; base < off1; base += 32) {
            int m = off1 - base; if (m > 32) m = 32;
            int   sv = 0; float nv = 0.f;
            if (lane < m) { sv = g_csrc[base + lane]; nv = g_cnorm[base + lane]; }
#pragma unroll 4
            for (int j = 0; j < m; j++) {
                int   ss = __shfl_sync(0xFFFFFFFFu, sv, j);
                float nn = __shfl_sync(0xFFFFFFFFu, nv, j);
                const float* r = g_xw1 + (long)ss * H1;
                a0 += r[lane]      * nn;
                a1 += r[lane + 32] * nn;
            }
        }
        g_h1[db + lane]      = a0;
        g_h1[db + lane + 32] = a1;
        st0 += a0; sq0 += a0 * a0;
        st1 += a1; sq1 += a1 * a1;
    }

    // stats: per-lane column sums -> shared -> one flush per block
    atomicAdd(&s_sum[lane],      st0);
    atomicAdd(&s_sum[lane + 32], st1);
    atomicAdd(&s_sq[lane],       sq0);
    atomicAdd(&s_sq[lane + 32],  sq1);
    __syncthreads();
    if (tid < H1) {
        atomicAdd(&g_sum1[tid], s_sum[tid]);
        atomicAdd(&g_sq1[tid],  s_sq[tid]);
    }
}

template <int H>
__global__ void k_bnfin(const float* __restrict__ sum, const float* __restrict__ sq,
                        const float* __restrict__ g, const float* __restrict__ be,
                        float* __restrict__ scale, float* __restrict__ shift, int n) {
    int i = threadIdx.x;
    if (i < H) {
        float m = sum[i] / (float)n;
        float v = sq[i] / (float)n - m * m;
        float s = g[i] * rsqrtf(v + 1e-5f);
        scale[i] = s;
        shift[i] = be[i] - m * s;
    }
}

// xw2 = relu(bn1(h1)) @ W2.  Row-per-thread.
__global__ __launch_bounds__(256) void k_gemm2(const float* __restrict__ W2, int n) {
    __shared__ float ws[H1 * H2];  // 8 KB
    __shared__ float s1[H1], t1[H1];
    int tid = threadIdx.x;
    for (int i = tid; i < H1 * H2; i += blockDim.x) ws[i] = W2[i];
    if (tid < H1) { s1[tid] = g_scale1[tid]; t1[tid] = g_shift1[tid]; }
    __syncthreads();

    int row = blockIdx.x * blockDim.x + tid;
    if (row >= n) return;

    float acc[H2];
#pragma unroll
    for (int c = 0; c < H2; c++) acc[c] = 0.f;

    const float4* ar = (const float4*)(g_h1 + (long)row * H1);
#pragma unroll 1
    for (int kb = 0; kb < H1 / 4; kb++) {
        float4 av = ar[kb];
        float vv[4] = {av.x, av.y, av.z, av.w};
#pragma unroll
        for (int u = 0; u < 4; u++) {
            int k = kb * 4 + u;
            float v = fmaxf(vv[u] * s1[k] + t1[k], 0.f);
            const float4* w = (const float4*)(ws + k * H2);
#pragma unroll
            for (int cq = 0; cq < H2 / 4; cq++) {
                float4 a0 = w[cq];
                acc[cq * 4 + 0] += v * a0.x;
                acc[cq * 4 + 1] += v * a0.y;
                acc[cq * 4 + 2] += v * a0.z;
                acc[cq * 4 + 3] += v * a0.w;
            }
        }
    }
    long base = (long)row * H2;
#pragma unroll
    for (int c = 0; c < H2; c++) g_xw2[base + c] = acc[c];
}

// Gather-aggregate layer2 (warp per node) + fused BN stats.
__global__ __launch_bounds__(256) void k_gather2(int n) {
    __shared__ float s_sum[H2], s_sq[H2];
    int tid  = threadIdx.x;
    int lane = tid & 31;
    if (tid < H2) { s_sum[tid] = 0.f; s_sq[tid] = 0.f; }
    __syncthreads();

    int wglob  = (blockIdx.x * blockDim.x + tid) >> 5;
    int nwarps = (gridDim.x * blockDim.x) >> 5;

    float st0 = 0.f, sq0 = 0.f;

    for (int d = wglob; d < n; d += nwarps) {
        float inv = g_invdeg[d];
        long  db  = (long)d * H2;
        float a0 = g_xw2[db + lane] * inv;

        int off0 = g_off[d], off1 = g_off[d + 1];
        for (int base = off0; base < off1; base += 32) {
            int m = off1 - base; if (m > 32) m = 32;
            int   sv = 0; float nv = 0.f;
            if (lane < m) { sv = g_csrc[base + lane]; nv = g_cnorm[base + lane]; }
#pragma unroll 4
            for (int j = 0; j < m; j++) {
                int   ss = __shfl_sync(0xFFFFFFFFu, sv, j);
                float nn = __shfl_sync(0xFFFFFFFFu, nv, j);
                a0 += g_xw2[(long)ss * H2 + lane] * nn;
            }
        }
        g_agg2[db + lane] = a0;
        st0 += a0; sq0 += a0 * a0;
    }

    atomicAdd(&s_sum[lane], st0);
    atomicAdd(&s_sq[lane],  sq0);
    __syncthreads();
    if (tid < H2) {
        atomicAdd(&g_sum2[tid], s_sum[tid]);
        atomicAdd(&g_sq2[tid],  s_sq[tid]);
    }
}

// out[row] = relu(bn2(agg2[row])) . Wl + bl   (warp per row)
__global__ void k_final(const float* __restrict__ Wl, const float* __restrict__ bl,
                        float* __restrict__ out, int n) {
    int gt   = blockIdx.x * blockDim.x + threadIdx.x;
    int row  = gt >> 5;
    int lane = gt & 31;
    if (row >= n) return;
    float v = g_agg2[(long)row * H2 + lane];
    v = fmaxf(v * g_scale2[lane] + g_shift2[lane], 0.f) * Wl[lane];
#pragma unroll
    for (int off = 16; off > 0; off >>= 1)
        v += __shfl_xor_sync(0xFFFFFFFFu, v, off);
    if (lane == 0) out[row] = v + bl[0];
}

// ---------------- launch ----------------
extern "C" void kernel_launch(void* const* d_in, const int* in_sizes, int n_in,
                              void* d_out, int out_size) {
    const float* x  = (const float*)d_in[0];
    const void*  ei = d_in[1];
    const float* ew = (const float*)d_in[2];
    const float* W1 = (const float*)d_in[3];
    const float* g1 = (const float*)d_in[5];
    const float* be1= (const float*)d_in[6];
    const float* W2 = (const float*)d_in[7];
    const float* g2 = (const float*)d_in[9];
    const float* be2= (const float*)d_in[10];
    const float* Wl = (const float*)d_in[11];
    const float* bl = (const float*)d_in[12];
    float* out = (float*)d_out;

    int n = in_sizes[0] / FIN;   // 100000
    int e = in_sizes[2];         // 1600000

    float *p_sum1, *p_sq1, *p_sc1, *p_sh1, *p_sum2, *p_sq2, *p_sc2, *p_sh2;
    cudaGetSymbolAddress((void**)&p_sum1, g_sum1);
    cudaGetSymbolAddress((void**)&p_sq1,  g_sq1);
    cudaGetSymbolAddress((void**)&p_sc1,  g_scale1);
    cudaGetSymbolAddress((void**)&p_sh1,  g_shift1);
    cudaGetSymbolAddress((void**)&p_sum2, g_sum2);
    cudaGetSymbolAddress((void**)&p_sq2,  g_sq2);
    cudaGetSymbolAddress((void**)&p_sc2,  g_scale2);
    cudaGetSymbolAddress((void**)&p_sh2,  g_shift2);

    int tb = 256;
    int gN  = (n + tb - 1) / tb;
    int gE  = (e + tb - 1) / tb;
    int gNw = (int)(((long)n * 32 + tb - 1) / tb);  // warp per row
    int nsb = (n + SCAN_B - 1) / SCAN_B;            // scan blocks (<=128)

    k_detect<<<1, 32>>>(ei, n, e);
    k_zero<<<gN, tb>>>(n);
    k_hist<<<gE, tb>>>(ei, ew, e);
    k_degfin<<<gN, tb>>>(n);

    k_scan1<<<nsb, SCAN_B>>>(n);
    k_scan2<<<1, 128>>>(nsb);
    k_scan3<<<gN, tb>>>(n, e);
    k_fill<<<gE, tb>>>(ei, ew, e);

    k_gemm1<<<gN, tb>>>(x, W1, n);
    k_gather1<<<1024, tb>>>(n);
    k_bnfin<H1><<<1, H1>>>(p_sum1, p_sq1, g1, be1, p_sc1, p_sh1, n);

    k_gemm2<<<gN, tb>>>(W2, n);
    k_gather2<<<1024, tb>>>(n);
    k_bnfin<H2><<<1, H2>>>(p_sum2, p_sq2, g2, be2, p_sc2, p_sh2, n);

    k_final<<<gNw, tb>>>(Wl, bl, out, n);
}

// round 6
// speedup vs baseline: 2.2925x; 1.1523x over previous
#include <cuda_runtime.h>

#define FIN 128
#define H1  64
#define H2  32
#define MAXN 100000
#define MAXE 1600000
#define SCAN_B 1024

// ---------------- device scratch (no allocations allowed) ----------------
__device__ float g_deg[MAXN];
__device__ float g_dinv[MAXN];
__device__ float g_invdeg[MAXN];
__device__ float g_xw1[MAXN * H1];
__device__ float g_h1[MAXN * H1];     // post-aggregation layer1 (pre-BN)
__device__ float g_xw2[MAXN * H2];
__device__ float g_agg2[MAXN * H2];
__device__ float g_sum1[H1], g_sq1[H1], g_scale1[H1], g_shift1[H1];
__device__ float g_sum2[H2], g_sq2[H2], g_scale2[H2], g_shift2[H2];
__device__ int   g_idx64;
// CSR
__device__ int   g_cnt[MAXN];
__device__ int   g_off[MAXN + 1];
__device__ int   g_cur[MAXN];
__device__ int2  g_cedge[MAXE];       // (src, __float_as_int(norm))
__device__ int   g_bsum[128];
__device__ int   g_carry[128];

// ---------------- helpers ----------------
__device__ __forceinline__ int load_src(const void* ei, int e, int i) {
    return g_idx64 ? (int)((const long long*)ei)[i] : ((const int*)ei)[i];
}
__device__ __forceinline__ int load_dst(const void* ei, int e, int i) {
    return g_idx64 ? (int)((const long long*)ei)[e + i] : ((const int*)ei)[e + i];
}
// Packed fp32x2 FMA (FFMA2): d = a*b + d  (2 MACs / instruction)
__device__ __forceinline__ void ffma2(unsigned long long& d,
                                      unsigned long long a, unsigned long long b) {
    asm("fma.rn.f32x2 %0, %1, %2, %0;" : "+l"(d) : "l"(a), "l"(b));
}
__device__ __forceinline__ unsigned long long bcast2(float v) {
    unsigned long long r; unsigned u = __float_as_uint(v);
    asm("mov.b64 %0, {%1, %1};" : "=l"(r) : "r"(u));
    return r;
}

// ---------------- kernels ----------------

// Detect whether edge_index is int64 or int32 (deterministic, data-driven).
__global__ void k_detect(const void* ei, int n, int e) {
    if (threadIdx.x == 0 && blockIdx.x == 0) {
        const long long* p = (const long long*)ei;
        int m = e < 512 ? e : 512;
        int ok = 1;
        for (int i = 0; i < m; i++) {
            unsigned long long v = (unsigned long long)p[i];
            if (v >= (unsigned long long)n) { ok = 0; break; }
        }
        g_idx64 = ok;
    }
}

__global__ void k_zero(int n) {
    int i = blockIdx.x * blockDim.x + threadIdx.x;
    if (i < n) { g_deg[i] = 0.f; g_cnt[i] = 0; }
    if (i < H1) { g_sum1[i] = 0.f; g_sq1[i] = 0.f; }
    if (i < H2) { g_sum2[i] = 0.f; g_sq2[i] = 0.f; }
}

// Weighted in-degree + integer in-degree histogram, one edge pass.
__global__ void k_hist(const void* ei, const float* __restrict__ ew, int e) {
    int i = blockIdx.x * blockDim.x + threadIdx.x;
    if (i >= e) return;
    int d = load_dst(ei, e, i);
    atomicAdd(&g_deg[d], ew[i]);
    atomicAdd(&g_cnt[d], 1);
}

__global__ void k_degfin(int n) {
    int i = blockIdx.x * blockDim.x + threadIdx.x;
    if (i >= n) return;
    float d = g_deg[i] + 1.0f;
    g_dinv[i]   = rsqrtf(d);
    g_invdeg[i] = 1.0f / d;
}

// ---- 3-phase exclusive scan over g_cnt -> g_off ----
__global__ __launch_bounds__(SCAN_B) void k_scan1(int n) {
    __shared__ int sh[SCAN_B];
    int i = blockIdx.x * SCAN_B + threadIdx.x;
    int v = (i < n) ? g_cnt[i] : 0;
    sh[threadIdx.x] = v;
    __syncthreads();
    for (int o = 1; o < SCAN_B; o <<= 1) {
        int t = (threadIdx.x >= o) ? sh[threadIdx.x - o] : 0;
        __syncthreads();
        sh[threadIdx.x] += t;
        __syncthreads();
    }
    if (i < n) g_off[i] = sh[threadIdx.x] - v;   // exclusive
    if (threadIdx.x == SCAN_B - 1) g_bsum[blockIdx.x] = sh[threadIdx.x];
}

__global__ void k_scan2(int nb) {
    __shared__ int sh[128];
    int tid = threadIdx.x;
    sh[tid] = (tid < nb) ? g_bsum[tid] : 0;
    __syncthreads();
    if (tid == 0) {
        int acc = 0;
        for (int b = 0; b < nb; b++) { int t = sh[b]; g_carry[b] = acc; acc += t; }
    }
}

__global__ void k_scan3(int n, int e) {
    int i = blockIdx.x * blockDim.x + threadIdx.x;
    if (i < n) {
        int v = g_off[i] + g_carry[i / SCAN_B];
        g_off[i] = v;
        g_cur[i] = v;
    }
    if (i == 0) g_off[n] = e;
}

// Fill CSR: one int2 (src, norm) slot per edge, bucketed by dst.
__global__ void k_fill(const void* ei, const float* __restrict__ ew, int e) {
    int i = blockIdx.x * blockDim.x + threadIdx.x;
    if (i >= e) return;
    int s = load_src(ei, e, i);
    int d = load_dst(ei, e, i);
    int p = atomicAdd(&g_cur[d], 1);
    float nrm = g_dinv[s] * ew[i] * g_dinv[d];
    g_cedge[p] = make_int2(s, __float_as_int(nrm));
}

// xw1 = x @ W1.  Row-per-thread, packed f32x2 FMA (FFMA2).
__global__ __launch_bounds__(256) void k_gemm1(const float* __restrict__ x,
                                               const float* __restrict__ W1, int n) {
    __shared__ float ws[FIN * H1];  // 32 KB
    int tid = threadIdx.x;
    for (int i = tid; i < FIN * H1 / 4; i += blockDim.x)
        ((float4*)ws)[i] = ((const float4*)W1)[i];
    __syncthreads();

    int row = blockIdx.x * blockDim.x + tid;
    if (row >= n) return;

    unsigned long long acc[H1 / 2];
#pragma unroll
    for (int c = 0; c < H1 / 2; c++) acc[c] = 0ull;

    const float4* xr = (const float4*)(x + (long)row * FIN);
#pragma unroll 1
    for (int kb = 0; kb < FIN / 4; kb++) {
        float4 xv = xr[kb];
        float xs[4] = {xv.x, xv.y, xv.z, xv.w};
#pragma unroll
        for (int u = 0; u < 4; u++) {
            unsigned long long xx = bcast2(xs[u]);
            const ulonglong2* w = (const ulonglong2*)(ws + (kb * 4 + u) * H1);
#pragma unroll
            for (int cq = 0; cq < H1 / 4; cq++) {
                ulonglong2 wv = w[cq];
                ffma2(acc[cq * 2],     xx, wv.x);
                ffma2(acc[cq * 2 + 1], xx, wv.y);
            }
        }
    }
    ulonglong2* outp = (ulonglong2*)(g_xw1 + (long)row * H1);
#pragma unroll
    for (int c = 0; c < H1 / 4; c++) {
        ulonglong2 v; v.x = acc[c * 2]; v.y = acc[c * 2 + 1];
        outp[c] = v;
    }
}

// Gather-aggregate layer1: warp per node, 2 edges per iteration,
// each half-warp loads one source row as 16 x float4. Fused BN stats.
__global__ __launch_bounds__(256) void k_gather1(int n) {
    __shared__ float s_sum[H1], s_sq[H1];
    int tid  = threadIdx.x;
    int lane = tid & 31;
    int half = lane >> 4;
    int hl   = lane & 15;
    if (tid < H1) { s_sum[tid] = 0.f; s_sq[tid] = 0.f; }
    __syncthreads();

    int wglob  = (blockIdx.x * blockDim.x + tid) >> 5;
    int nwarps = (gridDim.x * blockDim.x) >> 5;

    float4 st = make_float4(0.f, 0.f, 0.f, 0.f);
    float4 sq = make_float4(0.f, 0.f, 0.f, 0.f);

    for (int d = wglob; d < n; d += nwarps) {
        long  db  = (long)d * H1;
        float4 a = make_float4(0.f, 0.f, 0.f, 0.f);
        if (half == 0) {
            float inv = g_invdeg[d];
            float4 xv = ((const float4*)(g_xw1 + db))[hl];
            a.x = xv.x * inv; a.y = xv.y * inv; a.z = xv.z * inv; a.w = xv.w * inv;
        }

        int off0 = g_off[d], off1 = g_off[d + 1];
        for (int base = off0; base < off1; base += 32) {
            int m = off1 - base; if (m > 32) m = 32;
            int2 ed = (lane < m) ? g_cedge[base + lane] : make_int2(0, 0);
            int mp = (m + 1) & ~1;
#pragma unroll 2
            for (int jj = 0; jj < mp; jj += 2) {
                int j = jj + half;
                int   ss = __shfl_sync(0xFFFFFFFFu, ed.x, j);
                float nn = __int_as_float(__shfl_sync(0xFFFFFFFFu, ed.y, j));
                float4 v = ((const float4*)(g_xw1 + (long)ss * H1))[hl];
                a.x += v.x * nn; a.y += v.y * nn; a.z += v.z * nn; a.w += v.w * nn;
            }
        }
        // combine the two halves
        a.x += __shfl_down_sync(0xFFFFFFFFu, a.x, 16);
        a.y += __shfl_down_sync(0xFFFFFFFFu, a.y, 16);
        a.z += __shfl_down_sync(0xFFFFFFFFu, a.z, 16);
        a.w += __shfl_down_sync(0xFFFFFFFFu, a.w, 16);
        if (half == 0) {
            ((float4*)(g_h1 + db))[hl] = a;
            st.x += a.x; st.y += a.y; st.z += a.z; st.w += a.w;
            sq.x += a.x * a.x; sq.y += a.y * a.y; sq.z += a.z * a.z; sq.w += a.w * a.w;
        }
    }

    if (half == 0) {
        atomicAdd(&s_sum[hl * 4 + 0], st.x);
        atomicAdd(&s_sum[hl * 4 + 1], st.y);
        atomicAdd(&s_sum[hl * 4 + 2], st.z);
        atomicAdd(&s_sum[hl * 4 + 3], st.w);
        atomicAdd(&s_sq[hl * 4 + 0],  sq.x);
        atomicAdd(&s_sq[hl * 4 + 1],  sq.y);
        atomicAdd(&s_sq[hl * 4 + 2],  sq.z);
        atomicAdd(&s_sq[hl * 4 + 3],  sq.w);
    }
    __syncthreads();
    if (tid < H1) {
        atomicAdd(&g_sum1[tid], s_sum[tid]);
        atomicAdd(&g_sq1[tid],  s_sq[tid]);
    }
}

template <int H>
__global__ void k_bnfin(const float* __restrict__ sum, const float* __restrict__ sq,
                        const float* __restrict__ g, const float* __restrict__ be,
                        float* __restrict__ scale, float* __restrict__ shift, int n) {
    int i = threadIdx.x;
    if (i < H) {
        float m = sum[i] / (float)n;
        float v = sq[i] / (float)n - m * m;
        float s = g[i] * rsqrtf(v + 1e-5f);
        scale[i] = s;
        shift[i] = be[i] - m * s;
    }
}

// xw2 = relu(bn1(h1)) @ W2.  Row-per-thread, FFMA2.
__global__ __launch_bounds__(256) void k_gemm2(const float* __restrict__ W2, int n) {
    __shared__ float ws[H1 * H2];  // 8 KB
    __shared__ float s1[H1], t1[H1];
    int tid = threadIdx.x;
    for (int i = tid; i < H1 * H2; i += blockDim.x) ws[i] = W2[i];
    if (tid < H1) { s1[tid] = g_scale1[tid]; t1[tid] = g_shift1[tid]; }
    __syncthreads();

    int row = blockIdx.x * blockDim.x + tid;
    if (row >= n) return;

    unsigned long long acc[H2 / 2];
#pragma unroll
    for (int c = 0; c < H2 / 2; c++) acc[c] = 0ull;

    const float4* ar = (const float4*)(g_h1 + (long)row * H1);
#pragma unroll 1
    for (int kb = 0; kb < H1 / 4; kb++) {
        float4 av = ar[kb];
        float vv[4] = {av.x, av.y, av.z, av.w};
#pragma unroll
        for (int u = 0; u < 4; u++) {
            int k = kb * 4 + u;
            float v = fmaxf(vv[u] * s1[k] + t1[k], 0.f);
            unsigned long long xx = bcast2(v);
            const ulonglong2* w = (const ulonglong2*)(ws + k * H2);
#pragma unroll
            for (int cq = 0; cq < H2 / 4; cq++) {
                ulonglong2 wv = w[cq];
                ffma2(acc[cq * 2],     xx, wv.x);
                ffma2(acc[cq * 2 + 1], xx, wv.y);
            }
        }
    }
    ulonglong2* outp = (ulonglong2*)(g_xw2 + (long)row * H2);
#pragma unroll
    for (int c = 0; c < H2 / 4; c++) {
        ulonglong2 v; v.x = acc[c * 2]; v.y = acc[c * 2 + 1];
        outp[c] = v;
    }
}

// Gather-aggregate layer2: warp per node, 4 edges per iteration,
// each 8-lane group loads one source row as 8 x float4. Fused BN stats.
__global__ __launch_bounds__(256) void k_gather2(int n) {
    __shared__ float s_sum[H2], s_sq[H2];
    int tid  = threadIdx.x;
    int lane = tid & 31;
    int quad = lane >> 3;
    int ql   = lane & 7;
    if (tid < H2) { s_sum[tid] = 0.f; s_sq[tid] = 0.f; }
    __syncthreads();

    int wglob  = (blockIdx.x * blockDim.x + tid) >> 5;
    int nwarps = (gridDim.x * blockDim.x) >> 5;

    float4 st = make_float4(0.f, 0.f, 0.f, 0.f);
    float4 sq = make_float4(0.f, 0.f, 0.f, 0.f);

    for (int d = wglob; d < n; d += nwarps) {
        long  db = (long)d * H2;
        float4 a = make_float4(0.f, 0.f, 0.f, 0.f);
        if (quad == 0) {
            float inv = g_invdeg[d];
            float4 xv = ((const float4*)(g_xw2 + db))[ql];
            a.x = xv.x * inv; a.y = xv.y * inv; a.z = xv.z * inv; a.w = xv.w * inv;
        }

        int off0 = g_off[d], off1 = g_off[d + 1];
        for (int base = off0; base < off1; base += 32) {
            int m = off1 - base; if (m > 32) m = 32;
            int2 ed = (lane < m) ? g_cedge[base + lane] : make_int2(0, 0);
            int mp = (m + 3) & ~3;
#pragma unroll 2
            for (int jj = 0; jj < mp; jj += 4) {
                int j = jj + quad;
                int   ss = __shfl_sync(0xFFFFFFFFu, ed.x, j);
                float nn = __int_as_float(__shfl_sync(0xFFFFFFFFu, ed.y, j));
                float4 v = ((const float4*)(g_xw2 + (long)ss * H2))[ql];
                a.x += v.x * nn; a.y += v.y * nn; a.z += v.z * nn; a.w += v.w * nn;
            }
        }
        // combine the four quads
        a.x += __shfl_down_sync(0xFFFFFFFFu, a.x, 16);
        a.y += __shfl_down_sync(0xFFFFFFFFu, a.y, 16);
        a.z += __shfl_down_sync(0xFFFFFFFFu, a.z, 16);
        a.w += __shfl_down_sync(0xFFFFFFFFu, a.w, 16);
        a.x += __shfl_down_sync(0xFFFFFFFFu, a.x, 8);
        a.y += __shfl_down_sync(0xFFFFFFFFu, a.y, 8);
        a.z += __shfl_down_sync(0xFFFFFFFFu, a.z, 8);
        a.w += __shfl_down_sync(0xFFFFFFFFu, a.w, 8);
        if (quad == 0) {
            ((float4*)(g_agg2 + db))[ql] = a;
            st.x += a.x; st.y += a.y; st.z += a.z; st.w += a.w;
            sq.x += a.x * a.x; sq.y += a.y * a.y; sq.z += a.z * a.z; sq.w += a.w * a.w;
        }
    }

    if (quad == 0) {
        atomicAdd(&s_sum[ql * 4 + 0], st.x);
        atomicAdd(&s_sum[ql * 4 + 1], st.y);
        atomicAdd(&s_sum[ql * 4 + 2], st.z);
        atomicAdd(&s_sum[ql * 4 + 3], st.w);
        atomicAdd(&s_sq[ql * 4 + 0],  sq.x);
        atomicAdd(&s_sq[ql * 4 + 1],  sq.y);
        atomicAdd(&s_sq[ql * 4 + 2],  sq.z);
        atomicAdd(&s_sq[ql * 4 + 3],  sq.w);
    }
    __syncthreads();
    if (tid < H2) {
        atomicAdd(&g_sum2[tid], s_sum[tid]);
        atomicAdd(&g_sq2[tid],  s_sq[tid]);
    }
}

// out[row] = relu(bn2(agg2[row])) . Wl + bl   (warp per row)
__global__ void k_final(const float* __restrict__ Wl, const float* __restrict__ bl,
                        float* __restrict__ out, int n) {
    int gt   = blockIdx.x * blockDim.x + threadIdx.x;
    int row  = gt >> 5;
    int lane = gt & 31;
    if (row >= n) return;
    float v = g_agg2[(long)row * H2 + lane];
    v = fmaxf(v * g_scale2[lane] + g_shift2[lane], 0.f) * Wl[lane];
#pragma unroll
    for (int off = 16; off > 0; off >>= 1)
        v += __shfl_xor_sync(0xFFFFFFFFu, v, off);
    if (lane == 0) out[row] = v + bl[0];
}

// ---------------- launch ----------------
extern "C" void kernel_launch(void* const* d_in, const int* in_sizes, int n_in,
                              void* d_out, int out_size) {
    const float* x  = (const float*)d_in[0];
    const void*  ei = d_in[1];
    const float* ew = (const float*)d_in[2];
    const float* W1 = (const float*)d_in[3];
    const float* g1 = (const float*)d_in[5];
    const float* be1= (const float*)d_in[6];
    const float* W2 = (const float*)d_in[7];
    const float* g2 = (const float*)d_in[9];
    const float* be2= (const float*)d_in[10];
    const float* Wl = (const float*)d_in[11];
    const float* bl = (const float*)d_in[12];
    float* out = (float*)d_out;

    int n = in_sizes[0] / FIN;   // 100000
    int e = in_sizes[2];         // 1600000

    float *p_sum1, *p_sq1, *p_sc1, *p_sh1, *p_sum2, *p_sq2, *p_sc2, *p_sh2;
    cudaGetSymbolAddress((void**)&p_sum1, g_sum1);
    cudaGetSymbolAddress((void**)&p_sq1,  g_sq1);
    cudaGetSymbolAddress((void**)&p_sc1,  g_scale1);
    cudaGetSymbolAddress((void**)&p_sh1,  g_shift1);
    cudaGetSymbolAddress((void**)&p_sum2, g_sum2);
    cudaGetSymbolAddress((void**)&p_sq2,  g_sq2);
    cudaGetSymbolAddress((void**)&p_sc2,  g_scale2);
    cudaGetSymbolAddress((void**)&p_sh2,  g_shift2);

    int tb = 256;
    int gN  = (n + tb - 1) / tb;
    int gE  = (e + tb - 1) / tb;
    int gNw = (int)(((long)n * 32 + tb - 1) / tb);  // warp per row
    int nsb = (n + SCAN_B - 1) / SCAN_B;            // scan blocks (<=128)

    k_detect<<<1, 32>>>(ei, n, e);
    k_zero<<<gN, tb>>>(n);
    k_hist<<<gE, tb>>>(ei, ew, e);
    k_degfin<<<gN, tb>>>(n);

    k_scan1<<<nsb, SCAN_B>>>(n);
    k_scan2<<<1, 128>>>(nsb);
    k_scan3<<<gN, tb>>>(n, e);
    k_fill<<<gE, tb>>>(ei, ew, e);

    k_gemm1<<<gN, tb>>>(x, W1, n);
    k_gather1<<<1024, tb>>>(n);
    k_bnfin<H1><<<1, H1>>>(p_sum1, p_sq1, g1, be1, p_sc1, p_sh1, n);

    k_gemm2<<<gN, tb>>>(W2, n);
    k_gather2<<<1024, tb>>>(n);
    k_bnfin<H2><<<1, H2>>>(p_sum2, p_sq2, g2, be2, p_sc2, p_sh2, n);

    k_final<<<gNw, tb>>>(Wl, bl, out, n);
}

// round 7
// speedup vs baseline: 2.4358x; 1.0625x over previous
#include <cuda_runtime.h>

#define FIN 128
#define H1  64
#define H2  32
#define MAXN 100000
#define MAXE 1600000
#define SCAN_B 1024

// ---------------- device scratch (no allocations allowed) ----------------
__device__ float g_deg[MAXN];
__device__ float g_dinv[MAXN];
__device__ float g_invdeg[MAXN];
__device__ float g_xw1[MAXN * H1];
__device__ float g_h1[MAXN * H1];     // post-aggregation layer1 (pre-BN)
__device__ float g_xw2[MAXN * H2];
__device__ float g_agg2[MAXN * H2];
__device__ float g_sum1[H1], g_sq1[H1];
__device__ float g_sum2[H2], g_sq2[H2];
__device__ int   g_idx64;
// CSR
__device__ int   g_cnt[MAXN];
__device__ int   g_off[MAXN + 1];
__device__ int   g_cur[MAXN];
__device__ int2  g_cedge[MAXE];       // (src, __float_as_int(norm))
__device__ int   g_bsum[128];
__device__ int   g_carry[128];

typedef unsigned long long ull;

// ---------------- helpers ----------------
__device__ __forceinline__ int load_src(const void* ei, int e, int i) {
    return g_idx64 ? (int)((const long long*)ei)[i] : ((const int*)ei)[i];
}
__device__ __forceinline__ int load_dst(const void* ei, int e, int i) {
    return g_idx64 ? (int)((const long long*)ei)[e + i] : ((const int*)ei)[e + i];
}
// Packed fp32x2 FMA (FFMA2): d = a*b + d  (2 MACs / instruction)
__device__ __forceinline__ void ffma2(ull& d, ull a, ull b) {
    asm("fma.rn.f32x2 %0, %1, %2, %0;" : "+l"(d) : "l"(a), "l"(b));
}
__device__ __forceinline__ ull bcast2(float v) {
    ull r; unsigned u = __float_as_uint(v);
    asm("mov.b64 %0, {%1, %1};" : "=l"(r) : "r"(u));
    return r;
}

// ---------------- kernels ----------------

// Zero scratch + parallel int64/int32 detection (block 0).
__global__ void k_zero(const void* ei, int n, int e) {
    int i = blockIdx.x * blockDim.x + threadIdx.x;
    if (i < n) { g_deg[i] = 0.f; g_cnt[i] = 0; }
    if (i < H1) { g_sum1[i] = 0.f; g_sq1[i] = 0.f; }
    if (i < H2) { g_sum2[i] = 0.f; g_sq2[i] = 0.f; }

    if (blockIdx.x == 0) {
        __shared__ int sbad;
        if (threadIdx.x == 0) sbad = 0;
        __syncthreads();
        int m = e < 512 ? e : 512;
        int bad = 0;
        for (int k = threadIdx.x; k < m; k += blockDim.x) {
            unsigned long long v = ((const unsigned long long*)ei)[k];
            if (v >= (unsigned long long)n) bad = 1;
        }
        if (__any_sync(0xFFFFFFFFu, bad) && (threadIdx.x & 31) == 0)
            atomicOr(&sbad, 1);
        __syncthreads();
        if (threadIdx.x == 0) g_idx64 = sbad ? 0 : 1;
    }
}

// Weighted in-degree + integer in-degree histogram, one edge pass.
__global__ void k_hist(const void* ei, const float* __restrict__ ew, int e) {
    int i = blockIdx.x * blockDim.x + threadIdx.x;
    if (i >= e) return;
    int d = load_dst(ei, e, i);
    atomicAdd(&g_deg[d], ew[i]);
    atomicAdd(&g_cnt[d], 1);
}

// Warp-shuffle block scan over g_cnt -> g_off (exclusive), fused with degfin.
__global__ __launch_bounds__(SCAN_B) void k_scanA(int n) {
    __shared__ int wsum[32];
    int tid  = threadIdx.x;
    int lane = tid & 31, wid = tid >> 5;
    int i = blockIdx.x * SCAN_B + tid;
    int v = (i < n) ? g_cnt[i] : 0;

    int sc = v;
#pragma unroll
    for (int o = 1; o < 32; o <<= 1) {
        int t = __shfl_up_sync(0xFFFFFFFFu, sc, o);
        if (lane >= o) sc += t;
    }
    if (lane == 31) wsum[wid] = sc;
    __syncthreads();
    if (wid == 0) {
        int wv = wsum[lane];
#pragma unroll
        for (int o = 1; o < 32; o <<= 1) {
            int t = __shfl_up_sync(0xFFFFFFFFu, wv, o);
            if (lane >= o) wv += t;
        }
        wsum[lane] = wv;
    }
    __syncthreads();
    int incl = sc + (wid ? wsum[wid - 1] : 0);
    if (i < n) g_off[i] = incl - v;
    if (tid == SCAN_B - 1) g_bsum[blockIdx.x] = incl;

    // fused degfin (depends only on k_hist, same as the scan input)
    if (i < n) {
        float d = g_deg[i] + 1.0f;
        g_dinv[i]   = rsqrtf(d);
        g_invdeg[i] = 1.0f / d;
    }
}

__global__ void k_scan2(int nb) {
    __shared__ int sh[128];
    int tid = threadIdx.x;
    sh[tid] = (tid < nb) ? g_bsum[tid] : 0;
    __syncthreads();
    if (tid == 0) {
        int acc = 0;
        for (int b = 0; b < nb; b++) { int t = sh[b]; g_carry[b] = acc; acc += t; }
    }
}

__global__ void k_scan3(int n, int e) {
    int i = blockIdx.x * blockDim.x + threadIdx.x;
    if (i < n) {
        int v = g_off[i] + g_carry[i >> 10];
        g_off[i] = v;
        g_cur[i] = v;
    }
    if (i == 0) g_off[n] = e;
}

// Fill CSR: one int2 (src, norm) slot per edge, bucketed by dst.
__global__ void k_fill(const void* ei, const float* __restrict__ ew, int e) {
    int i = blockIdx.x * blockDim.x + threadIdx.x;
    if (i >= e) return;
    int s = load_src(ei, e, i);
    int d = load_dst(ei, e, i);
    int p = atomicAdd(&g_cur[d], 1);
    float nrm = g_dinv[s] * ew[i] * g_dinv[d];
    g_cedge[p] = make_int2(s, __float_as_int(nrm));
}

// xw1 = x @ W1.  2 rows per thread (each weight LDS feeds 4 FFMA2).
__global__ __launch_bounds__(128) void k_gemm1(const float* __restrict__ x,
                                               const float* __restrict__ W1, int n) {
    __shared__ float ws[FIN * H1];  // 32 KB
    int tid = threadIdx.x;
    for (int i = tid; i < FIN * H1 / 4; i += 128)
        ((float4*)ws)[i] = ((const float4*)W1)[i];
    __syncthreads();

    int r0 = blockIdx.x * 256 + tid;
    int r1 = r0 + 128;
    if (r0 >= n) return;
    bool has1 = (r1 < n);

    ull accA[H1 / 2], accB[H1 / 2];
#pragma unroll
    for (int c = 0; c < H1 / 2; c++) { accA[c] = 0ull; accB[c] = 0ull; }

    const float4* xa = (const float4*)(x + (long)r0 * FIN);
    const float4* xb = has1 ? (const float4*)(x + (long)r1 * FIN) : xa;
#pragma unroll 1
    for (int kb = 0; kb < FIN / 4; kb++) {
        float4 va = xa[kb], vb = xb[kb];
        float as[4] = {va.x, va.y, va.z, va.w};
        float bs[4] = {vb.x, vb.y, vb.z, vb.w};
#pragma unroll
        for (int u = 0; u < 4; u++) {
            ull ax = bcast2(as[u]);
            ull bx = bcast2(bs[u]);
            const ulonglong2* w = (const ulonglong2*)(ws + (kb * 4 + u) * H1);
#pragma unroll
            for (int cq = 0; cq < H1 / 4; cq++) {
                ulonglong2 wv = w[cq];
                ffma2(accA[cq * 2],     ax, wv.x);
                ffma2(accA[cq * 2 + 1], ax, wv.y);
                ffma2(accB[cq * 2],     bx, wv.x);
                ffma2(accB[cq * 2 + 1], bx, wv.y);
            }
        }
    }
    ulonglong2* oa = (ulonglong2*)(g_xw1 + (long)r0 * H1);
#pragma unroll
    for (int c = 0; c < H1 / 4; c++) {
        ulonglong2 v; v.x = accA[c * 2]; v.y = accA[c * 2 + 1];
        oa[c] = v;
    }
    if (has1) {
        ulonglong2* ob = (ulonglong2*)(g_xw1 + (long)r1 * H1);
#pragma unroll
        for (int c = 0; c < H1 / 4; c++) {
            ulonglong2 v; v.x = accB[c * 2]; v.y = accB[c * 2 + 1];
            ob[c] = v;
        }
    }
}

// Gather-aggregate layer1: warp per node, 2 edges per iteration,
// each half-warp loads one source row as 16 x float4. Fused BN stats.
__global__ __launch_bounds__(256) void k_gather1(int n) {
    __shared__ float s_sum[H1], s_sq[H1];
    int tid  = threadIdx.x;
    int lane = tid & 31;
    int half = lane >> 4;
    int hl   = lane & 15;
    if (tid < H1) { s_sum[tid] = 0.f; s_sq[tid] = 0.f; }
    __syncthreads();

    int wglob  = (blockIdx.x * blockDim.x + tid) >> 5;
    int nwarps = (gridDim.x * blockDim.x) >> 5;

    float4 st = make_float4(0.f, 0.f, 0.f, 0.f);
    float4 sq = make_float4(0.f, 0.f, 0.f, 0.f);

    for (int d = wglob; d < n; d += nwarps) {
        long  db = (long)d * H1;
        float4 a = make_float4(0.f, 0.f, 0.f, 0.f);
        if (half == 0) {
            float inv = g_invdeg[d];
            float4 xv = ((const float4*)(g_xw1 + db))[hl];
            a.x = xv.x * inv; a.y = xv.y * inv; a.z = xv.z * inv; a.w = xv.w * inv;
        }

        int off0 = g_off[d], off1 = g_off[d + 1];
        for (int base = off0; base < off1; base += 32) {
            int m = off1 - base; if (m > 32) m = 32;
            int2 ed = (lane < m) ? g_cedge[base + lane] : make_int2(0, 0);
            int mp = (m + 1) & ~1;
#pragma unroll 4
            for (int jj = 0; jj < mp; jj += 2) {
                int j = jj + half;
                int   ss = __shfl_sync(0xFFFFFFFFu, ed.x, j);
                float nn = __int_as_float(__shfl_sync(0xFFFFFFFFu, ed.y, j));
                float4 v = ((const float4*)(g_xw1 + (long)ss * H1))[hl];
                a.x += v.x * nn; a.y += v.y * nn; a.z += v.z * nn; a.w += v.w * nn;
            }
        }
        a.x += __shfl_down_sync(0xFFFFFFFFu, a.x, 16);
        a.y += __shfl_down_sync(0xFFFFFFFFu, a.y, 16);
        a.z += __shfl_down_sync(0xFFFFFFFFu, a.z, 16);
        a.w += __shfl_down_sync(0xFFFFFFFFu, a.w, 16);
        if (half == 0) {
            ((float4*)(g_h1 + db))[hl] = a;
            st.x += a.x; st.y += a.y; st.z += a.z; st.w += a.w;
            sq.x += a.x * a.x; sq.y += a.y * a.y; sq.z += a.z * a.z; sq.w += a.w * a.w;
        }
    }

    if (half == 0) {
        atomicAdd(&s_sum[hl * 4 + 0], st.x);
        atomicAdd(&s_sum[hl * 4 + 1], st.y);
        atomicAdd(&s_sum[hl * 4 + 2], st.z);
        atomicAdd(&s_sum[hl * 4 + 3], st.w);
        atomicAdd(&s_sq[hl * 4 + 0],  sq.x);
        atomicAdd(&s_sq[hl * 4 + 1],  sq.y);
        atomicAdd(&s_sq[hl * 4 + 2],  sq.z);
        atomicAdd(&s_sq[hl * 4 + 3],  sq.w);
    }
    __syncthreads();
    if (tid < H1) {
        atomicAdd(&g_sum1[tid], s_sum[tid]);
        atomicAdd(&g_sq1[tid],  s_sq[tid]);
    }
}

// xw2 = relu(bn1(h1)) @ W2.  2 rows per thread; BN1 finalize fused in prologue.
__global__ __launch_bounds__(256) void k_gemm2(const float* __restrict__ W2,
                                               const float* __restrict__ g1,
                                               const float* __restrict__ be1,
                                               int n, float invn) {
    __shared__ float ws[H1 * H2];  // 8 KB
    __shared__ float s1[H1], t1[H1];
    int tid = threadIdx.x;
    for (int i = tid; i < H1 * H2 / 4; i += 256)
        ((float4*)ws)[i] = ((const float4*)W2)[i];
    if (tid < H1) {
        float m = g_sum1[tid] * invn;
        float v = g_sq1[tid] * invn - m * m;
        float s = g1[tid] * rsqrtf(v + 1e-5f);
        s1[tid] = s;
        t1[tid] = be1[tid] - m * s;
    }
    __syncthreads();

    int r0 = blockIdx.x * 512 + tid;
    int r1 = r0 + 256;
    if (r0 >= n) return;
    bool has1 = (r1 < n);

    ull accA[H2 / 2], accB[H2 / 2];
#pragma unroll
    for (int c = 0; c < H2 / 2; c++) { accA[c] = 0ull; accB[c] = 0ull; }

    const float4* xa = (const float4*)(g_h1 + (long)r0 * H1);
    const float4* xb = has1 ? (const float4*)(g_h1 + (long)r1 * H1) : xa;
#pragma unroll 1
    for (int kb = 0; kb < H1 / 4; kb++) {
        float4 va = xa[kb], vb = xb[kb];
        float as[4] = {va.x, va.y, va.z, va.w};
        float bs[4] = {vb.x, vb.y, vb.z, vb.w};
#pragma unroll
        for (int u = 0; u < 4; u++) {
            int k = kb * 4 + u;
            float s = s1[k], t = t1[k];
            ull ax = bcast2(fmaxf(as[u] * s + t, 0.f));
            ull bx = bcast2(fmaxf(bs[u] * s + t, 0.f));
            const ulonglong2* w = (const ulonglong2*)(ws + k * H2);
#pragma unroll
            for (int cq = 0; cq < H2 / 4; cq++) {
                ulonglong2 wv = w[cq];
                ffma2(accA[cq * 2],     ax, wv.x);
                ffma2(accA[cq * 2 + 1], ax, wv.y);
                ffma2(accB[cq * 2],     bx, wv.x);
                ffma2(accB[cq * 2 + 1], bx, wv.y);
            }
        }
    }
    ulonglong2* oa = (ulonglong2*)(g_xw2 + (long)r0 * H2);
#pragma unroll
    for (int c = 0; c < H2 / 4; c++) {
        ulonglong2 v; v.x = accA[c * 2]; v.y = accA[c * 2 + 1];
        oa[c] = v;
    }
    if (has1) {
        ulonglong2* ob = (ulonglong2*)(g_xw2 + (long)r1 * H2);
#pragma unroll
        for (int c = 0; c < H2 / 4; c++) {
            ulonglong2 v; v.x = accB[c * 2]; v.y = accB[c * 2 + 1];
            ob[c] = v;
        }
    }
}

// Gather-aggregate layer2: warp per node, 4 edges per iteration,
// each 8-lane group loads one source row as 8 x float4. Fused BN stats.
__global__ __launch_bounds__(256) void k_gather2(int n) {
    __shared__ float s_sum[H2], s_sq[H2];
    int tid  = threadIdx.x;
    int lane = tid & 31;
    int quad = lane >> 3;
    int ql   = lane & 7;
    if (tid < H2) { s_sum[tid] = 0.f; s_sq[tid] = 0.f; }
    __syncthreads();

    int wglob  = (blockIdx.x * blockDim.x + tid) >> 5;
    int nwarps = (gridDim.x * blockDim.x) >> 5;

    float4 st = make_float4(0.f, 0.f, 0.f, 0.f);
    float4 sq = make_float4(0.f, 0.f, 0.f, 0.f);

    for (int d = wglob; d < n; d += nwarps) {
        long  db = (long)d * H2;
        float4 a = make_float4(0.f, 0.f, 0.f, 0.f);
        if (quad == 0) {
            float inv = g_invdeg[d];
            float4 xv = ((const float4*)(g_xw2 + db))[ql];
            a.x = xv.x * inv; a.y = xv.y * inv; a.z = xv.z * inv; a.w = xv.w * inv;
        }

        int off0 = g_off[d], off1 = g_off[d + 1];
        for (int base = off0; base < off1; base += 32) {
            int m = off1 - base; if (m > 32) m = 32;
            int2 ed = (lane < m) ? g_cedge[base + lane] : make_int2(0, 0);
            int mp = (m + 3) & ~3;
#pragma unroll 4
            for (int jj = 0; jj < mp; jj += 4) {
                int j = jj + quad;
                int   ss = __shfl_sync(0xFFFFFFFFu, ed.x, j);
                float nn = __int_as_float(__shfl_sync(0xFFFFFFFFu, ed.y, j));
                float4 v = ((const float4*)(g_xw2 + (long)ss * H2))[ql];
                a.x += v.x * nn; a.y += v.y * nn; a.z += v.z * nn; a.w += v.w * nn;
            }
        }
        a.x += __shfl_down_sync(0xFFFFFFFFu, a.x, 16);
        a.y += __shfl_down_sync(0xFFFFFFFFu, a.y, 16);
        a.z += __shfl_down_sync(0xFFFFFFFFu, a.z, 16);
        a.w += __shfl_down_sync(0xFFFFFFFFu, a.w, 16);
        a.x += __shfl_down_sync(0xFFFFFFFFu, a.x, 8);
        a.y += __shfl_down_sync(0xFFFFFFFFu, a.y, 8);
        a.z += __shfl_down_sync(0xFFFFFFFFu, a.z, 8);
        a.w += __shfl_down_sync(0xFFFFFFFFu, a.w, 8);
        if (quad == 0) {
            ((float4*)(g_agg2 + db))[ql] = a;
            st.x += a.x; st.y += a.y; st.z += a.z; st.w += a.w;
            sq.x += a.x * a.x; sq.y += a.y * a.y; sq.z += a.z * a.z; sq.w += a.w * a.w;
        }
    }

    if (quad == 0) {
        atomicAdd(&s_sum[ql * 4 + 0], st.x);
        atomicAdd(&s_sum[ql * 4 + 1], st.y);
        atomicAdd(&s_sum[ql * 4 + 2], st.z);
        atomicAdd(&s_sum[ql * 4 + 3], st.w);
        atomicAdd(&s_sq[ql * 4 + 0],  sq.x);
        atomicAdd(&s_sq[ql * 4 + 1],  sq.y);
        atomicAdd(&s_sq[ql * 4 + 2],  sq.z);
        atomicAdd(&s_sq[ql * 4 + 3],  sq.w);
    }
    __syncthreads();
    if (tid < H2) {
        atomicAdd(&g_sum2[tid], s_sum[tid]);
        atomicAdd(&g_sq2[tid],  s_sq[tid]);
    }
}

// out[row] = relu(bn2(agg2[row])) . Wl + bl.  8 lanes per row, float4 loads;
// BN2 finalize fused in prologue.
__global__ void k_final(const float* __restrict__ Wl, const float* __restrict__ bl,
                        const float* __restrict__ g2, const float* __restrict__ be2,
                        float* __restrict__ out, int n, float invn) {
    __shared__ float s2[H2], t2[H2];
    int tid = threadIdx.x;
    if (tid < H2) {
        float m = g_sum2[tid] * invn;
        float v = g_sq2[tid] * invn - m * m;
        float s = g2[tid] * rsqrtf(v + 1e-5f);
        s2[tid] = s;
        t2[tid] = be2[tid] - m * s;
    }
    __syncthreads();

    int gt  = blockIdx.x * blockDim.x + tid;
    int row = gt >> 3;
    int ql  = gt & 7;
    if (row >= n) return;

    float4 a  = ((const float4*)(g_agg2 + (long)row * H2))[ql];
    float4 sc = ((const float4*)s2)[ql];
    float4 sh = ((const float4*)t2)[ql];
    float4 wl = ((const float4*)Wl)[ql];
    float v = fmaxf(a.x * sc.x + sh.x, 0.f) * wl.x
            + fmaxf(a.y * sc.y + sh.y, 0.f) * wl.y
            + fmaxf(a.z * sc.z + sh.z, 0.f) * wl.z
            + fmaxf(a.w * sc.w + sh.w, 0.f) * wl.w;
    v += __shfl_down_sync(0xFFFFFFFFu, v, 4, 8);
    v += __shfl_down_sync(0xFFFFFFFFu, v, 2, 8);
    v += __shfl_down_sync(0xFFFFFFFFu, v, 1, 8);
    if (ql == 0) out[row] = v + bl[0];
}

// ---------------- launch ----------------
extern "C" void kernel_launch(void* const* d_in, const int* in_sizes, int n_in,
                              void* d_out, int out_size) {
    const float* x  = (const float*)d_in[0];
    const void*  ei = d_in[1];
    const float* ew = (const float*)d_in[2];
    const float* W1 = (const float*)d_in[3];
    const float* g1 = (const float*)d_in[5];
    const float* be1= (const float*)d_in[6];
    const float* W2 = (const float*)d_in[7];
    const float* g2 = (const float*)d_in[9];
    const float* be2= (const float*)d_in[10];
    const float* Wl = (const float*)d_in[11];
    const float* bl = (const float*)d_in[12];
    float* out = (float*)d_out;

    int n = in_sizes[0] / FIN;   // 100000
    int e = in_sizes[2];         // 1600000
    float invn = 1.0f / (float)n;

    int tb = 256;
    int gN   = (n + tb - 1) / tb;
    int gE   = (e + tb - 1) / tb;
    int gG1  = (n + 255) / 256;                     // gemm1: 128 thr, 256 rows/blk
    int gG2  = (n + 511) / 512;                     // gemm2: 256 thr, 512 rows/blk
    int gF   = (int)(((long)n * 8 + tb - 1) / tb);  // 8 lanes per row
    int nsb  = (n + SCAN_B - 1) / SCAN_B;           // scan blocks (<=128)

    k_zero<<<gN, tb>>>(ei, n, e);
    k_hist<<<gE, tb>>>(ei, ew, e);

    k_scanA<<<nsb, SCAN_B>>>(n);
    k_scan2<<<1, 128>>>(nsb);
    k_scan3<<<gN, tb>>>(n, e);
    k_fill<<<gE, tb>>>(ei, ew, e);

    k_gemm1<<<gG1, 128>>>(x, W1, n);
    k_gather1<<<1024, tb>>>(n);

    k_gemm2<<<gG2, tb>>>(W2, g1, be1, n, invn);
    k_gather2<<<1024, tb>>>(n);

    k_final<<<gF, tb>>>(Wl, bl, g2, be2, out, n, invn);
}

// round 8
// speedup vs baseline: 2.6249x; 1.0776x over previous
#include <cuda_runtime.h>

#define FIN 128
#define H1  64
#define H2  32
#define MAXN 100000
#define MAXE 1600000
#define SCAN_B 1024

typedef unsigned long long ull;

// ---------------- device scratch (no allocations allowed) ----------------
// Invariant: everything here is zero at kernel_launch entry (zeroed at module
// load; each run re-zeroes what it consumed before finishing).
__device__ float g_deg[MAXN];
__device__ float g_dinv[MAXN];
__device__ float g_invdeg[MAXN];
__device__ float g_xw1[MAXN * H1];
__device__ float g_h1[MAXN * H1];
__device__ float g_xw2[MAXN * H2];
__device__ float g_agg2[MAXN * H2];
__device__ float g_sum1[H1], g_sq1[H1];
__device__ float g_sum2[H2], g_sq2[H2];
// CSR
__device__ int   g_cnt[MAXN];
__device__ int   g_off[MAXN + 1];
__device__ int   g_cur[MAXN];
__device__ int2  g_cedge[MAXE];       // (src, __float_as_int(norm))
// decoupled-lookback scan state (reset by last block each run)
__device__ long long g_stat[128];     // (sum<<2)|code  code:1=agg,2=prefix
__device__ int   g_ticket;
__device__ int   g_done;

// ---------------- helpers ----------------
// Packed fp32x2 FMA (FFMA2): d = a*b + d  (2 MACs / instruction)
__device__ __forceinline__ void ffma2(ull& d, ull a, ull b) {
    asm("fma.rn.f32x2 %0, %1, %2, %0;" : "+l"(d) : "l"(a), "l"(b));
}
__device__ __forceinline__ ull bcast2(float v) {
    ull r; unsigned u = __float_as_uint(v);
    asm("mov.b64 %0, {%1, %1};" : "=l"(r) : "r"(u));
    return r;
}

// Per-block int64/int32 detection: deterministic, identical verdict in every
// block. First 256 int64 words all < n  <=>  indices are int64.
// Requires blockDim.x == 256; ALL threads must call (has barriers).
__device__ __forceinline__ int detect64(const void* ei, int n, int e) {
    __shared__ int sflag;
    int tid = threadIdx.x;
    if (tid == 0) sflag = 0;
    __syncthreads();
    int m = e < 256 ? e : 256;
    int bad = 0;
    if (tid < m) {
        unsigned long long v = ((const unsigned long long*)ei)[tid];
        bad = (v >= (unsigned long long)n) ? 1 : 0;
    }
    unsigned b = __ballot_sync(0xFFFFFFFFu, bad);
    if ((tid & 31) == 0 && b) atomicOr(&sflag, 1);
    __syncthreads();
    return sflag ? 0 : 1;
}

// ---------------- kernels ----------------

// Weighted in-degree + integer in-degree histogram, one edge pass.
__global__ void k_hist(const void* ei, const float* __restrict__ ew, int n, int e) {
    int is64 = detect64(ei, n, e);
    int i = blockIdx.x * blockDim.x + threadIdx.x;
    if (i >= e) return;
    int d = is64 ? (int)((const long long*)ei)[e + i] : ((const int*)ei)[e + i];
    atomicAdd(&g_deg[d], ew[i]);
    atomicAdd(&g_cnt[d], 1);
}

// Fused: decoupled-lookback exclusive scan (g_cnt -> g_off, g_cur),
// degfin (dinv/invdeg), g_off[n]=e, and re-zero of g_deg/g_cnt.
__global__ __launch_bounds__(SCAN_B) void k_scanF(int n, int e) {
    __shared__ int wsum[32];
    __shared__ int sbid, sexc, stot;
    int tid  = threadIdx.x;
    int lane = tid & 31, wid = tid >> 5;

    if (tid == 0) sbid = atomicAdd(&g_ticket, 1);
    __syncthreads();
    int bid = sbid;
    int i = bid * SCAN_B + tid;

    int v = (i < n) ? g_cnt[i] : 0;

    // block-local inclusive scan (warp shuffle)
    int sc = v;
#pragma unroll
    for (int o = 1; o < 32; o <<= 1) {
        int t = __shfl_up_sync(0xFFFFFFFFu, sc, o);
        if (lane >= o) sc += t;
    }
    if (lane == 31) wsum[wid] = sc;
    __syncthreads();
    if (wid == 0) {
        int wv = wsum[lane];
#pragma unroll
        for (int o = 1; o < 32; o <<= 1) {
            int t = __shfl_up_sync(0xFFFFFFFFu, wv, o);
            if (lane >= o) wv += t;
        }
        wsum[lane] = wv;
    }
    __syncthreads();
    int incl = sc + (wid ? wsum[wid - 1] : 0);
    if (tid == SCAN_B - 1) {
        stot = incl;
        if (bid > 0)  // publish aggregate (prefix publish below for bid 0 too)
            ((volatile long long*)g_stat)[bid] = ((long long)incl << 2) | 1;
    }
    __syncthreads();
    int total = stot;

    // lookback (thread 0)
    if (tid == 0) {
        int exc = 0;
        if (bid > 0) {
            int j = bid - 1;
            while (true) {
                long long s = ((volatile long long*)g_stat)[j];
                int code = (int)(s & 3);
                if (code == 0) continue;
                exc += (int)(s >> 2);
                if (code == 2) break;
                j--;
            }
        }
        sexc = exc;
        ((volatile long long*)g_stat)[bid] = ((long long)(exc + total) << 2) | 2;
    }
    __syncthreads();
    int exc = sexc;

    if (i < n) {
        int off = exc + incl - v;
        g_off[i] = off;
        g_cur[i] = off;
        // fused degfin + re-zero for next replay
        float dg = g_deg[i] + 1.0f;
        g_dinv[i]   = rsqrtf(dg);
        g_invdeg[i] = 1.0f / dg;
        g_deg[i] = 0.f;
        g_cnt[i] = 0;
    }
    if (bid == 0 && tid == 0) g_off[n] = e;

    // last block resets scan state for the next replay
    if (tid == 0) {
        __threadfence();
        int c = atomicAdd(&g_done, 1);
        if (c == (int)gridDim.x - 1) {
            for (int j = 0; j < (int)gridDim.x; j++) g_stat[j] = 0;
            g_ticket = 0;
            g_done = 0;
        }
    }
}

// Fill CSR: one int2 (src, norm) slot per edge, bucketed by dst.
__global__ void k_fill(const void* ei, const float* __restrict__ ew, int n, int e) {
    int is64 = detect64(ei, n, e);
    int i = blockIdx.x * blockDim.x + threadIdx.x;
    if (i >= e) return;
    int s, d;
    if (is64) {
        s = (int)((const long long*)ei)[i];
        d = (int)((const long long*)ei)[e + i];
    } else {
        s = ((const int*)ei)[i];
        d = ((const int*)ei)[e + i];
    }
    int p = atomicAdd(&g_cur[d], 1);
    float nrm = g_dinv[s] * ew[i] * g_dinv[d];
    g_cedge[p] = make_int2(s, __float_as_int(nrm));
}

// xw1 = x @ W1.  2 rows per thread (each weight LDS feeds 4 FFMA2).
__global__ __launch_bounds__(128) void k_gemm1(const float* __restrict__ x,
                                               const float* __restrict__ W1, int n) {
    __shared__ float ws[FIN * H1];  // 32 KB
    int tid = threadIdx.x;
    for (int i = tid; i < FIN * H1 / 4; i += 128)
        ((float4*)ws)[i] = ((const float4*)W1)[i];
    __syncthreads();

    int r0 = blockIdx.x * 256 + tid;
    int r1 = r0 + 128;
    if (r0 >= n) return;
    bool has1 = (r1 < n);

    ull accA[H1 / 2], accB[H1 / 2];
#pragma unroll
    for (int c = 0; c < H1 / 2; c++) { accA[c] = 0ull; accB[c] = 0ull; }

    const float4* xa = (const float4*)(x + (long)r0 * FIN);
    const float4* xb = has1 ? (const float4*)(x + (long)r1 * FIN) : xa;
#pragma unroll 1
    for (int kb = 0; kb < FIN / 4; kb++) {
        float4 va = xa[kb], vb = xb[kb];
        float as[4] = {va.x, va.y, va.z, va.w};
        float bs[4] = {vb.x, vb.y, vb.z, vb.w};
#pragma unroll
        for (int u = 0; u < 4; u++) {
            ull ax = bcast2(as[u]);
            ull bx = bcast2(bs[u]);
            const ulonglong2* w = (const ulonglong2*)(ws + (kb * 4 + u) * H1);
#pragma unroll
            for (int cq = 0; cq < H1 / 4; cq++) {
                ulonglong2 wv = w[cq];
                ffma2(accA[cq * 2],     ax, wv.x);
                ffma2(accA[cq * 2 + 1], ax, wv.y);
                ffma2(accB[cq * 2],     bx, wv.x);
                ffma2(accB[cq * 2 + 1], bx, wv.y);
            }
        }
    }
    ulonglong2* oa = (ulonglong2*)(g_xw1 + (long)r0 * H1);
#pragma unroll
    for (int c = 0; c < H1 / 4; c++) {
        ulonglong2 v; v.x = accA[c * 2]; v.y = accA[c * 2 + 1];
        oa[c] = v;
    }
    if (has1) {
        ulonglong2* ob = (ulonglong2*)(g_xw1 + (long)r1 * H1);
#pragma unroll
        for (int c = 0; c < H1 / 4; c++) {
            ulonglong2 v; v.x = accB[c * 2]; v.y = accB[c * 2 + 1];
            ob[c] = v;
        }
    }
}

// Gather-aggregate layer1: warp per node, 2 edges in flight (one per half-warp),
// direct broadcast loads of edge records (no shuffles). Fused BN stats.
__global__ __launch_bounds__(256) void k_gather1(int n) {
    __shared__ float s_sum[H1], s_sq[H1];
    int tid  = threadIdx.x;
    int lane = tid & 31;
    int half = lane >> 4;
    int hl   = lane & 15;
    if (tid < H1) { s_sum[tid] = 0.f; s_sq[tid] = 0.f; }
    __syncthreads();

    int wglob  = (blockIdx.x * blockDim.x + tid) >> 5;
    int nwarps = (gridDim.x * blockDim.x) >> 5;

    float4 st = make_float4(0.f, 0.f, 0.f, 0.f);
    float4 sq = make_float4(0.f, 0.f, 0.f, 0.f);

    for (int d = wglob; d < n; d += nwarps) {
        long  db = (long)d * H1;
        float4 a = make_float4(0.f, 0.f, 0.f, 0.f);
        if (half == 0) {
            float inv = g_invdeg[d];
            float4 xv = ((const float4*)(g_xw1 + db))[hl];
            a.x = xv.x * inv; a.y = xv.y * inv; a.z = xv.z * inv; a.w = xv.w * inv;
        }

        int off0 = g_off[d], off1 = g_off[d + 1];
#pragma unroll 4
        for (int j0 = off0; j0 < off1; j0 += 2) {
            int j = j0 + half;
            if (j < off1) {
                int2 ed = g_cedge[j];
                float nn = __int_as_float(ed.y);
                float4 v = ((const float4*)(g_xw1 + (long)ed.x * H1))[hl];
                a.x += v.x * nn; a.y += v.y * nn; a.z += v.z * nn; a.w += v.w * nn;
            }
        }
        a.x += __shfl_down_sync(0xFFFFFFFFu, a.x, 16);
        a.y += __shfl_down_sync(0xFFFFFFFFu, a.y, 16);
        a.z += __shfl_down_sync(0xFFFFFFFFu, a.z, 16);
        a.w += __shfl_down_sync(0xFFFFFFFFu, a.w, 16);
        if (half == 0) {
            ((float4*)(g_h1 + db))[hl] = a;
            st.x += a.x; st.y += a.y; st.z += a.z; st.w += a.w;
            sq.x += a.x * a.x; sq.y += a.y * a.y; sq.z += a.z * a.z; sq.w += a.w * a.w;
        }
    }

    if (half == 0) {
        atomicAdd(&s_sum[hl * 4 + 0], st.x);
        atomicAdd(&s_sum[hl * 4 + 1], st.y);
        atomicAdd(&s_sum[hl * 4 + 2], st.z);
        atomicAdd(&s_sum[hl * 4 + 3], st.w);
        atomicAdd(&s_sq[hl * 4 + 0],  sq.x);
        atomicAdd(&s_sq[hl * 4 + 1],  sq.y);
        atomicAdd(&s_sq[hl * 4 + 2],  sq.z);
        atomicAdd(&s_sq[hl * 4 + 3],  sq.w);
    }
    __syncthreads();
    if (tid < H1) {
        atomicAdd(&g_sum1[tid], s_sum[tid]);
        atomicAdd(&g_sq1[tid],  s_sq[tid]);
    }
}

// xw2 = relu(bn1(h1)) @ W2.  2 rows/thread; BN1 finalize in prologue;
// block 0 re-zeroes g_sum2/g_sq2 for this run's gather2.
__global__ __launch_bounds__(256) void k_gemm2(const float* __restrict__ W2,
                                               const float* __restrict__ g1,
                                               const float* __restrict__ be1,
                                               int n, float invn) {
    __shared__ float ws[H1 * H2];  // 8 KB
    __shared__ float s1[H1], t1[H1];
    int tid = threadIdx.x;
    for (int i = tid; i < H1 * H2 / 4; i += 256)
        ((float4*)ws)[i] = ((const float4*)W2)[i];
    if (tid < H1) {
        float m = g_sum1[tid] * invn;
        float v = g_sq1[tid] * invn - m * m;
        float s = g1[tid] * rsqrtf(v + 1e-5f);
        s1[tid] = s;
        t1[tid] = be1[tid] - m * s;
    }
    if (blockIdx.x == 0 && tid < H2) { g_sum2[tid] = 0.f; g_sq2[tid] = 0.f; }
    __syncthreads();

    int r0 = blockIdx.x * 512 + tid;
    int r1 = r0 + 256;
    if (r0 >= n) return;
    bool has1 = (r1 < n);

    ull accA[H2 / 2], accB[H2 / 2];
#pragma unroll
    for (int c = 0; c < H2 / 2; c++) { accA[c] = 0ull; accB[c] = 0ull; }

    const float4* xa = (const float4*)(g_h1 + (long)r0 * H1);
    const float4* xb = has1 ? (const float4*)(g_h1 + (long)r1 * H1) : xa;
#pragma unroll 1
    for (int kb = 0; kb < H1 / 4; kb++) {
        float4 va = xa[kb], vb = xb[kb];
        float as[4] = {va.x, va.y, va.z, va.w};
        float bs[4] = {vb.x, vb.y, vb.z, vb.w};
#pragma unroll
        for (int u = 0; u < 4; u++) {
            int k = kb * 4 + u;
            float s = s1[k], t = t1[k];
            ull ax = bcast2(fmaxf(as[u] * s + t, 0.f));
            ull bx = bcast2(fmaxf(bs[u] * s + t, 0.f));
            const ulonglong2* w = (const ulonglong2*)(ws + k * H2);
#pragma unroll
            for (int cq = 0; cq < H2 / 4; cq++) {
                ulonglong2 wv = w[cq];
                ffma2(accA[cq * 2],     ax, wv.x);
                ffma2(accA[cq * 2 + 1], ax, wv.y);
                ffma2(accB[cq * 2],     bx, wv.x);
                ffma2(accB[cq * 2 + 1], bx, wv.y);
            }
        }
    }
    ulonglong2* oa = (ulonglong2*)(g_xw2 + (long)r0 * H2);
#pragma unroll
    for (int c = 0; c < H2 / 4; c++) {
        ulonglong2 v; v.x = accA[c * 2]; v.y = accA[c * 2 + 1];
        oa[c] = v;
    }
    if (has1) {
        ulonglong2* ob = (ulonglong2*)(g_xw2 + (long)r1 * H2);
#pragma unroll
        for (int c = 0; c < H2 / 4; c++) {
            ulonglong2 v; v.x = accB[c * 2]; v.y = accB[c * 2 + 1];
            ob[c] = v;
        }
    }
}

// Gather-aggregate layer2: warp per node, 4 edges in flight (one per 8-lane
// group), direct broadcast loads. Fused BN stats.
__global__ __launch_bounds__(256) void k_gather2(int n) {
    __shared__ float s_sum[H2], s_sq[H2];
    int tid  = threadIdx.x;
    int lane = tid & 31;
    int quad = lane >> 3;
    int ql   = lane & 7;
    if (tid < H2) { s_sum[tid] = 0.f; s_sq[tid] = 0.f; }
    __syncthreads();

    int wglob  = (blockIdx.x * blockDim.x + tid) >> 5;
    int nwarps = (gridDim.x * blockDim.x) >> 5;

    float4 st = make_float4(0.f, 0.f, 0.f, 0.f);
    float4 sq = make_float4(0.f, 0.f, 0.f, 0.f);

    for (int d = wglob; d < n; d += nwarps) {
        long  db = (long)d * H2;
        float4 a = make_float4(0.f, 0.f, 0.f, 0.f);
        if (quad == 0) {
            float inv = g_invdeg[d];
            float4 xv = ((const float4*)(g_xw2 + db))[ql];
            a.x = xv.x * inv; a.y = xv.y * inv; a.z = xv.z * inv; a.w = xv.w * inv;
        }

        int off0 = g_off[d], off1 = g_off[d + 1];
#pragma unroll 4
        for (int j0 = off0; j0 < off1; j0 += 4) {
            int j = j0 + quad;
            if (j < off1) {
                int2 ed = g_cedge[j];
                float nn = __int_as_float(ed.y);
                float4 v = ((const float4*)(g_xw2 + (long)ed.x * H2))[ql];
                a.x += v.x * nn; a.y += v.y * nn; a.z += v.z * nn; a.w += v.w * nn;
            }
        }
        a.x += __shfl_down_sync(0xFFFFFFFFu, a.x, 16);
        a.y += __shfl_down_sync(0xFFFFFFFFu, a.y, 16);
        a.z += __shfl_down_sync(0xFFFFFFFFu, a.z, 16);
        a.w += __shfl_down_sync(0xFFFFFFFFu, a.w, 16);
        a.x += __shfl_down_sync(0xFFFFFFFFu, a.x, 8);
        a.y += __shfl_down_sync(0xFFFFFFFFu, a.y, 8);
        a.z += __shfl_down_sync(0xFFFFFFFFu, a.z, 8);
        a.w += __shfl_down_sync(0xFFFFFFFFu, a.w, 8);
        if (quad == 0) {
            ((float4*)(g_agg2 + db))[ql] = a;
            st.x += a.x; st.y += a.y; st.z += a.z; st.w += a.w;
            sq.x += a.x * a.x; sq.y += a.y * a.y; sq.z += a.z * a.z; sq.w += a.w * a.w;
        }
    }

    if (quad == 0) {
        atomicAdd(&s_sum[ql * 4 + 0], st.x);
        atomicAdd(&s_sum[ql * 4 + 1], st.y);
        atomicAdd(&s_sum[ql * 4 + 2], st.z);
        atomicAdd(&s_sum[ql * 4 + 3], st.w);
        atomicAdd(&s_sq[ql * 4 + 0],  sq.x);
        atomicAdd(&s_sq[ql * 4 + 1],  sq.y);
        atomicAdd(&s_sq[ql * 4 + 2],  sq.z);
        atomicAdd(&s_sq[ql * 4 + 3],  sq.w);
    }
    __syncthreads();
    if (tid < H2) {
        atomicAdd(&g_sum2[tid], s_sum[tid]);
        atomicAdd(&g_sq2[tid],  s_sq[tid]);
    }
}

// out[row] = relu(bn2(agg2[row])) . Wl + bl.  8 lanes/row; BN2 finalize in
// prologue; block 0 re-zeroes g_sum1/g_sq1 for the next replay's gather1.
__global__ void k_final(const float* __restrict__ Wl, const float* __restrict__ bl,
                        const float* __restrict__ g2, const float* __restrict__ be2,
                        float* __restrict__ out, int n, float invn) {
    __shared__ float s2[H2], t2[H2];
    int tid = threadIdx.x;
    if (tid < H2) {
        float m = g_sum2[tid] * invn;
        float v = g_sq2[tid] * invn - m * m;
        float s = g2[tid] * rsqrtf(v + 1e-5f);
        s2[tid] = s;
        t2[tid] = be2[tid] - m * s;
    }
    if (blockIdx.x == 0 && tid < H1) { g_sum1[tid] = 0.f; g_sq1[tid] = 0.f; }
    __syncthreads();

    int gt  = blockIdx.x * blockDim.x + tid;
    int row = gt >> 3;
    int ql  = gt & 7;
    if (row >= n) return;

    float4 a  = ((const float4*)(g_agg2 + (long)row * H2))[ql];
    float4 sc = ((const float4*)s2)[ql];
    float4 sh = ((const float4*)t2)[ql];
    float4 wl = ((const float4*)Wl)[ql];
    float v = fmaxf(a.x * sc.x + sh.x, 0.f) * wl.x
            + fmaxf(a.y * sc.y + sh.y, 0.f) * wl.y
            + fmaxf(a.z * sc.z + sh.z, 0.f) * wl.z
            + fmaxf(a.w * sc.w + sh.w, 0.f) * wl.w;
    v += __shfl_down_sync(0xFFFFFFFFu, v, 4, 8);
    v += __shfl_down_sync(0xFFFFFFFFu, v, 2, 8);
    v += __shfl_down_sync(0xFFFFFFFFu, v, 1, 8);
    if (ql == 0) out[row] = v + bl[0];
}

// ---------------- launch ----------------
extern "C" void kernel_launch(void* const* d_in, const int* in_sizes, int n_in,
                              void* d_out, int out_size) {
    const float* x  = (const float*)d_in[0];
    const void*  ei = d_in[1];
    const float* ew = (const float*)d_in[2];
    const float* W1 = (const float*)d_in[3];
    const float* g1 = (const float*)d_in[5];
    const float* be1= (const float*)d_in[6];
    const float* W2 = (const float*)d_in[7];
    const float* g2 = (const float*)d_in[9];
    const float* be2= (const float*)d_in[10];
    const float* Wl = (const float*)d_in[11];
    const float* bl = (const float*)d_in[12];
    float* out = (float*)d_out;

    int n = in_sizes[0] / FIN;   // 100000
    int e = in_sizes[2];         // 1600000
    float invn = 1.0f / (float)n;

    int tb = 256;
    int gE   = (e + tb - 1) / tb;
    int gG1  = (n + 255) / 256;                     // gemm1: 128 thr, 256 rows/blk
    int gG2  = (n + 511) / 512;                     // gemm2: 256 thr, 512 rows/blk
    int gF   = (int)(((long)n * 8 + tb - 1) / tb);  // 8 lanes per row
    int nsb  = (n + SCAN_B - 1) / SCAN_B;           // scan blocks (<=128)

    k_hist<<<gE, tb>>>(ei, ew, n, e);
    k_scanF<<<nsb, SCAN_B>>>(n, e);
    k_fill<<<gE, tb>>>(ei, ew, n, e);

    k_gemm1<<<gG1, 128>>>(x, W1, n);
    k_gather1<<<1024, tb>>>(n);

    k_gemm2<<<gG2, tb>>>(W2, g1, be1, n, invn);
    k_gather2<<<1024, tb>>>(n);

    k_final<<<gF, tb>>>(Wl, bl, g2, be2, out, n, invn);
}

// round 9
// speedup vs baseline: 2.7299x; 1.0400x over previous
#include <cuda_runtime.h>

#define FIN 128
#define H1  64
#define H2  32
#define MAXN 100000
#define MAXE 1600000
#define SCAN_B 1024

typedef unsigned long long ull;

// ---------------- device scratch (no allocations allowed) ----------------
// Invariant: everything here is zero at kernel_launch entry (zeroed at module
// load; each run re-zeroes what it consumed before finishing).
__device__ float g_deg[MAXN];
__device__ float g_dinv[MAXN];
__device__ float g_invdeg[MAXN];
__device__ float g_xw1[MAXN * H1];
__device__ float g_h1[MAXN * H1];
__device__ float g_xw2[MAXN * H2];
__device__ float g_agg2[MAXN * H2];
__device__ float g_sum1[H1], g_sq1[H1];
__device__ float g_sum2[H2], g_sq2[H2];
// CSR
__device__ int   g_cnt[MAXN];
__device__ int   g_off[MAXN + 1];
__device__ int   g_cur[MAXN];
__device__ int2  g_cedge[MAXE];       // (src, __float_as_int(norm))
// decoupled-lookback scan state (reset by last block each run)
__device__ long long g_stat[128];     // (sum<<2)|code  code:1=agg,2=prefix
__device__ int   g_ticket;
__device__ int   g_done;

// ---------------- helpers ----------------
// Packed fp32x2 FMA (FFMA2): d = a*b + d  (2 MACs / instruction)
__device__ __forceinline__ void ffma2(ull& d, ull a, ull b) {
    asm("fma.rn.f32x2 %0, %1, %2, %0;" : "+l"(d) : "l"(a), "l"(b));
}
__device__ __forceinline__ ull bcast2(float v) {
    ull r; unsigned u = __float_as_uint(v);
    asm("mov.b64 %0, {%1, %1};" : "=l"(r) : "r"(u));
    return r;
}

// Per-block int64/int32 detection: deterministic, identical verdict in every
// block. First 256 int64 words all < n  <=>  indices are int64.
// Requires blockDim.x == 256; ALL threads of the block must call.
__device__ __forceinline__ int detect64(const void* ei, int n, int e) {
    __shared__ int sflag;
    int tid = threadIdx.x;
    if (tid == 0) sflag = 0;
    __syncthreads();
    int m = e < 256 ? e : 256;
    int bad = 0;
    if (tid < m) {
        unsigned long long v = ((const unsigned long long*)ei)[tid];
        bad = (v >= (unsigned long long)n) ? 1 : 0;
    }
    unsigned b = __ballot_sync(0xFFFFFFFFu, bad);
    if ((tid & 31) == 0 && b) atomicOr(&sflag, 1);
    __syncthreads();
    return sflag ? 0 : 1;
}

// ---------------- kernels ----------------

// Fused launch: blocks [0, gB) compute xw1 = x @ W1 (1 row/thread, FFMA2,
// prefetched x); blocks [gB, gB+HB) run the edge histogram (independent DAG
// roots — hist work hides under gemm's latency slack).
__global__ __launch_bounds__(256, 2) void k_pre(
    const float* __restrict__ x, const float* __restrict__ W1,
    const void* ei, const float* __restrict__ ew,
    int n, int e, int gB, int HB) {
    int tid = threadIdx.x;

    if (blockIdx.x >= gB) {
        // ---- histogram role ----
        int is64 = detect64(ei, n, e);
        int start  = (blockIdx.x - gB) * 256 + tid;
        int stride = HB * 256;
        if (is64) {
            const long long* dd = (const long long*)ei + e;
            for (int i = start; i < e; i += stride) {
                int d = (int)dd[i];
                atomicAdd(&g_deg[d], ew[i]);
                atomicAdd(&g_cnt[d], 1);
            }
        } else {
            const int* dd = (const int*)ei + e;
            for (int i = start; i < e; i += stride) {
                int d = dd[i];
                atomicAdd(&g_deg[d], ew[i]);
                atomicAdd(&g_cnt[d], 1);
            }
        }
        return;
    }

    // ---- gemm role: 1 row per thread ----
    __shared__ float ws[FIN * H1];  // 32 KB
    for (int i = tid; i < FIN * H1 / 4; i += 256)
        ((float4*)ws)[i] = ((const float4*)W1)[i];
    __syncthreads();

    int row = blockIdx.x * 256 + tid;
    if (row >= n) return;

    ull acc[H1 / 2];
#pragma unroll
    for (int c = 0; c < H1 / 2; c++) acc[c] = 0ull;

    const float4* xr = (const float4*)(x + (long)row * FIN);
    float4 xv = xr[0];
#pragma unroll 1
    for (int kb = 0; kb < FIN / 4; kb++) {
        float4 xn = xv;
        if (kb < FIN / 4 - 1) xn = xr[kb + 1];   // prefetch next chunk
        float xs[4] = {xv.x, xv.y, xv.z, xv.w};
#pragma unroll
        for (int u = 0; u < 4; u++) {
            ull ax = bcast2(xs[u]);
            const ulonglong2* w = (const ulonglong2*)(ws + (kb * 4 + u) * H1);
#pragma unroll
            for (int cq = 0; cq < H1 / 4; cq++) {
                ulonglong2 wv = w[cq];
                ffma2(acc[cq * 2],     ax, wv.x);
                ffma2(acc[cq * 2 + 1], ax, wv.y);
            }
        }
        xv = xn;
    }
    ulonglong2* o = (ulonglong2*)(g_xw1 + (long)row * H1);
#pragma unroll
    for (int c = 0; c < H1 / 4; c++) {
        ulonglong2 v; v.x = acc[c * 2]; v.y = acc[c * 2 + 1];
        o[c] = v;
    }
}

// Fused: decoupled-lookback exclusive scan (g_cnt -> g_off, g_cur),
// degfin (dinv/invdeg), g_off[n]=e, and re-zero of g_deg/g_cnt.
__global__ __launch_bounds__(SCAN_B) void k_scanF(int n, int e) {
    __shared__ int wsum[32];
    __shared__ int sbid, sexc, stot;
    int tid  = threadIdx.x;
    int lane = tid & 31, wid = tid >> 5;

    if (tid == 0) sbid = atomicAdd(&g_ticket, 1);
    __syncthreads();
    int bid = sbid;
    int i = bid * SCAN_B + tid;

    int v = (i < n) ? g_cnt[i] : 0;

    int sc = v;
#pragma unroll
    for (int o = 1; o < 32; o <<= 1) {
        int t = __shfl_up_sync(0xFFFFFFFFu, sc, o);
        if (lane >= o) sc += t;
    }
    if (lane == 31) wsum[wid] = sc;
    __syncthreads();
    if (wid == 0) {
        int wv = wsum[lane];
#pragma unroll
        for (int o = 1; o < 32; o <<= 1) {
            int t = __shfl_up_sync(0xFFFFFFFFu, wv, o);
            if (lane >= o) wv += t;
        }
        wsum[lane] = wv;
    }
    __syncthreads();
    int incl = sc + (wid ? wsum[wid - 1] : 0);
    if (tid == SCAN_B - 1) {
        stot = incl;
        if (bid > 0)
            ((volatile long long*)g_stat)[bid] = ((long long)incl << 2) | 1;
    }
    __syncthreads();
    int total = stot;

    if (tid == 0) {
        int exc = 0;
        if (bid > 0) {
            int j = bid - 1;
            while (true) {
                long long s = ((volatile long long*)g_stat)[j];
                int code = (int)(s & 3);
                if (code == 0) continue;
                exc += (int)(s >> 2);
                if (code == 2) break;
                j--;
            }
        }
        sexc = exc;
        ((volatile long long*)g_stat)[bid] = ((long long)(exc + total) << 2) | 2;
    }
    __syncthreads();
    int exc = sexc;

    if (i < n) {
        int off = exc + incl - v;
        g_off[i] = off;
        g_cur[i] = off;
        float dg = g_deg[i] + 1.0f;
        g_dinv[i]   = rsqrtf(dg);
        g_invdeg[i] = 1.0f / dg;
        g_deg[i] = 0.f;
        g_cnt[i] = 0;
    }
    if (bid == 0 && tid == 0) g_off[n] = e;

    if (tid == 0) {
        __threadfence();
        int c = atomicAdd(&g_done, 1);
        if (c == (int)gridDim.x - 1) {
            for (int j = 0; j < (int)gridDim.x; j++) g_stat[j] = 0;
            g_ticket = 0;
            g_done = 0;
        }
    }
}

// Fill CSR: one int2 (src, norm) slot per edge, bucketed by dst.
__global__ void k_fill(const void* ei, const float* __restrict__ ew, int n, int e) {
    int is64 = detect64(ei, n, e);
    int i = blockIdx.x * blockDim.x + threadIdx.x;
    if (i >= e) return;
    int s, d;
    if (is64) {
        s = (int)((const long long*)ei)[i];
        d = (int)((const long long*)ei)[e + i];
    } else {
        s = ((const int*)ei)[i];
        d = ((const int*)ei)[e + i];
    }
    int p = atomicAdd(&g_cur[d], 1);
    float nrm = g_dinv[s] * ew[i] * g_dinv[d];
    g_cedge[p] = make_int2(s, __float_as_int(nrm));
}

// Gather-aggregate layer1: warp per node, 2 edges in flight (one per half-warp),
// direct broadcast loads of edge records. Fused BN stats.
__global__ __launch_bounds__(256) void k_gather1(int n) {
    __shared__ float s_sum[H1], s_sq[H1];
    int tid  = threadIdx.x;
    int lane = tid & 31;
    int half = lane >> 4;
    int hl   = lane & 15;
    if (tid < H1) { s_sum[tid] = 0.f; s_sq[tid] = 0.f; }
    __syncthreads();

    int wglob  = (blockIdx.x * blockDim.x + tid) >> 5;
    int nwarps = (gridDim.x * blockDim.x) >> 5;

    float4 st = make_float4(0.f, 0.f, 0.f, 0.f);
    float4 sq = make_float4(0.f, 0.f, 0.f, 0.f);

    for (int d = wglob; d < n; d += nwarps) {
        long  db = (long)d * H1;
        float4 a = make_float4(0.f, 0.f, 0.f, 0.f);
        if (half == 0) {
            float inv = g_invdeg[d];
            float4 xv = ((const float4*)(g_xw1 + db))[hl];
            a.x = xv.x * inv; a.y = xv.y * inv; a.z = xv.z * inv; a.w = xv.w * inv;
        }

        int off0 = g_off[d], off1 = g_off[d + 1];
#pragma unroll 4
        for (int j0 = off0; j0 < off1; j0 += 2) {
            int j = j0 + half;
            if (j < off1) {
                int2 ed = g_cedge[j];
                float nn = __int_as_float(ed.y);
                float4 v = ((const float4*)(g_xw1 + (long)ed.x * H1))[hl];
                a.x += v.x * nn; a.y += v.y * nn; a.z += v.z * nn; a.w += v.w * nn;
            }
        }
        a.x += __shfl_down_sync(0xFFFFFFFFu, a.x, 16);
        a.y += __shfl_down_sync(0xFFFFFFFFu, a.y, 16);
        a.z += __shfl_down_sync(0xFFFFFFFFu, a.z, 16);
        a.w += __shfl_down_sync(0xFFFFFFFFu, a.w, 16);
        if (half == 0) {
            ((float4*)(g_h1 + db))[hl] = a;
            st.x += a.x; st.y += a.y; st.z += a.z; st.w += a.w;
            sq.x += a.x * a.x; sq.y += a.y * a.y; sq.z += a.z * a.z; sq.w += a.w * a.w;
        }
    }

    if (half == 0) {
        atomicAdd(&s_sum[hl * 4 + 0], st.x);
        atomicAdd(&s_sum[hl * 4 + 1], st.y);
        atomicAdd(&s_sum[hl * 4 + 2], st.z);
        atomicAdd(&s_sum[hl * 4 + 3], st.w);
        atomicAdd(&s_sq[hl * 4 + 0],  sq.x);
        atomicAdd(&s_sq[hl * 4 + 1],  sq.y);
        atomicAdd(&s_sq[hl * 4 + 2],  sq.z);
        atomicAdd(&s_sq[hl * 4 + 3],  sq.w);
    }
    __syncthreads();
    if (tid < H1) {
        atomicAdd(&g_sum1[tid], s_sum[tid]);
        atomicAdd(&g_sq1[tid],  s_sq[tid]);
    }
}

// xw2 = relu(bn1(h1)) @ W2.  2 rows/thread; BN1 finalize in prologue;
// block 0 re-zeroes g_sum2/g_sq2 for this run's gather2.
__global__ __launch_bounds__(256) void k_gemm2(const float* __restrict__ W2,
                                               const float* __restrict__ g1,
                                               const float* __restrict__ be1,
                                               int n, float invn) {
    __shared__ float ws[H1 * H2];  // 8 KB
    __shared__ float s1[H1], t1[H1];
    int tid = threadIdx.x;
    for (int i = tid; i < H1 * H2 / 4; i += 256)
        ((float4*)ws)[i] = ((const float4*)W2)[i];
    if (tid < H1) {
        float m = g_sum1[tid] * invn;
        float v = g_sq1[tid] * invn - m * m;
        float s = g1[tid] * rsqrtf(v + 1e-5f);
        s1[tid] = s;
        t1[tid] = be1[tid] - m * s;
    }
    if (blockIdx.x == 0 && tid < H2) { g_sum2[tid] = 0.f; g_sq2[tid] = 0.f; }
    __syncthreads();

    int r0 = blockIdx.x * 512 + tid;
    int r1 = r0 + 256;
    if (r0 >= n) return;
    bool has1 = (r1 < n);

    ull accA[H2 / 2], accB[H2 / 2];
#pragma unroll
    for (int c = 0; c < H2 / 2; c++) { accA[c] = 0ull; accB[c] = 0ull; }

    const float4* xa = (const float4*)(g_h1 + (long)r0 * H1);
    const float4* xb = has1 ? (const float4*)(g_h1 + (long)r1 * H1) : xa;
#pragma unroll 1
    for (int kb = 0; kb < H1 / 4; kb++) {
        float4 va = xa[kb], vb = xb[kb];
        float as[4] = {va.x, va.y, va.z, va.w};
        float bs[4] = {vb.x, vb.y, vb.z, vb.w};
#pragma unroll
        for (int u = 0; u < 4; u++) {
            int k = kb * 4 + u;
            float s = s1[k], t = t1[k];
            ull ax = bcast2(fmaxf(as[u] * s + t, 0.f));
            ull bx = bcast2(fmaxf(bs[u] * s + t, 0.f));
            const ulonglong2* w = (const ulonglong2*)(ws + k * H2);
#pragma unroll
            for (int cq = 0; cq < H2 / 4; cq++) {
                ulonglong2 wv = w[cq];
                ffma2(accA[cq * 2],     ax, wv.x);
                ffma2(accA[cq * 2 + 1], ax, wv.y);
                ffma2(accB[cq * 2],     bx, wv.x);
                ffma2(accB[cq * 2 + 1], bx, wv.y);
            }
        }
    }
    ulonglong2* oa = (ulonglong2*)(g_xw2 + (long)r0 * H2);
#pragma unroll
    for (int c = 0; c < H2 / 4; c++) {
        ulonglong2 v; v.x = accA[c * 2]; v.y = accA[c * 2 + 1];
        oa[c] = v;
    }
    if (has1) {
        ulonglong2* ob = (ulonglong2*)(g_xw2 + (long)r1 * H2);
#pragma unroll
        for (int c = 0; c < H2 / 4; c++) {
            ulonglong2 v; v.x = accB[c * 2]; v.y = accB[c * 2 + 1];
            ob[c] = v;
        }
    }
}

// Gather-aggregate layer2: warp per node, 4 edges in flight (one per 8-lane
// group), direct broadcast loads. Fused BN stats.
__global__ __launch_bounds__(256) void k_gather2(int n) {
    __shared__ float s_sum[H2], s_sq[H2];
    int tid  = threadIdx.x;
    int lane = tid & 31;
    int quad = lane >> 3;
    int ql   = lane & 7;
    if (tid < H2) { s_sum[tid] = 0.f; s_sq[tid] = 0.f; }
    __syncthreads();

    int wglob  = (blockIdx.x * blockDim.x + tid) >> 5;
    int nwarps = (gridDim.x * blockDim.x) >> 5;

    float4 st = make_float4(0.f, 0.f, 0.f, 0.f);
    float4 sq = make_float4(0.f, 0.f, 0.f, 0.f);

    for (int d = wglob; d < n; d += nwarps) {
        long  db = (long)d * H2;
        float4 a = make_float4(0.f, 0.f, 0.f, 0.f);
        if (quad == 0) {
            float inv = g_invdeg[d];
            float4 xv = ((const float4*)(g_xw2 + db))[ql];
            a.x = xv.x * inv; a.y = xv.y * inv; a.z = xv.z * inv; a.w = xv.w * inv;
        }

        int off0 = g_off[d], off1 = g_off[d + 1];
#pragma unroll 4
        for (int j0 = off0; j0 < off1; j0 += 4) {
            int j = j0 + quad;
            if (j < off1) {
                int2 ed = g_cedge[j];
                float nn = __int_as_float(ed.y);
                float4 v = ((const float4*)(g_xw2 + (long)ed.x * H2))[ql];
                a.x += v.x * nn; a.y += v.y * nn; a.z += v.z * nn; a.w += v.w * nn;
            }
        }
        a.x += __shfl_down_sync(0xFFFFFFFFu, a.x, 16);
        a.y += __shfl_down_sync(0xFFFFFFFFu, a.y, 16);
        a.z += __shfl_down_sync(0xFFFFFFFFu, a.z, 16);
        a.w += __shfl_down_sync(0xFFFFFFFFu, a.w, 16);
        a.x += __shfl_down_sync(0xFFFFFFFFu, a.x, 8);
        a.y += __shfl_down_sync(0xFFFFFFFFu, a.y, 8);
        a.z += __shfl_down_sync(0xFFFFFFFFu, a.z, 8);
        a.w += __shfl_down_sync(0xFFFFFFFFu, a.w, 8);
        if (quad == 0) {
            ((float4*)(g_agg2 + db))[ql] = a;
            st.x += a.x; st.y += a.y; st.z += a.z; st.w += a.w;
            sq.x += a.x * a.x; sq.y += a.y * a.y; sq.z += a.z * a.z; sq.w += a.w * a.w;
        }
    }

    if (quad == 0) {
        atomicAdd(&s_sum[ql * 4 + 0], st.x);
        atomicAdd(&s_sum[ql * 4 + 1], st.y);
        atomicAdd(&s_sum[ql * 4 + 2], st.z);
        atomicAdd(&s_sum[ql * 4 + 3], st.w);
        atomicAdd(&s_sq[ql * 4 + 0],  sq.x);
        atomicAdd(&s_sq[ql * 4 + 1],  sq.y);
        atomicAdd(&s_sq[ql * 4 + 2],  sq.z);
        atomicAdd(&s_sq[ql * 4 + 3],  sq.w);
    }
    __syncthreads();
    if (tid < H2) {
        atomicAdd(&g_sum2[tid], s_sum[tid]);
        atomicAdd(&g_sq2[tid],  s_sq[tid]);
    }
}

// out[row] = relu(bn2(agg2[row])) . Wl + bl.  8 lanes/row; BN2 finalize in
// prologue; block 0 re-zeroes g_sum1/g_sq1 for the next replay's gather1.
__global__ void k_final(const float* __restrict__ Wl, const float* __restrict__ bl,
                        const float* __restrict__ g2, const float* __restrict__ be2,
                        float* __restrict__ out, int n, float invn) {
    __shared__ float s2[H2], t2[H2];
    int tid = threadIdx.x;
    if (tid < H2) {
        float m = g_sum2[tid] * invn;
        float v = g_sq2[tid] * invn - m * m;
        float s = g2[tid] * rsqrtf(v + 1e-5f);
        s2[tid] = s;
        t2[tid] = be2[tid] - m * s;
    }
    if (blockIdx.x == 0 && tid < H1) { g_sum1[tid] = 0.f; g_sq1[tid] = 0.f; }
    __syncthreads();

    int gt  = blockIdx.x * blockDim.x + tid;
    int row = gt >> 3;
    int ql  = gt & 7;
    if (row >= n) return;

    float4 a  = ((const float4*)(g_agg2 + (long)row * H2))[ql];
    float4 sc = ((const float4*)s2)[ql];
    float4 sh = ((const float4*)t2)[ql];
    float4 wl = ((const float4*)Wl)[ql];
    float v = fmaxf(a.x * sc.x + sh.x, 0.f) * wl.x
            + fmaxf(a.y * sc.y + sh.y, 0.f) * wl.y
            + fmaxf(a.z * sc.z + sh.z, 0.f) * wl.z
            + fmaxf(a.w * sc.w + sh.w, 0.f) * wl.w;
    v += __shfl_down_sync(0xFFFFFFFFu, v, 4, 8);
    v += __shfl_down_sync(0xFFFFFFFFu, v, 2, 8);
    v += __shfl_down_sync(0xFFFFFFFFu, v, 1, 8);
    if (ql == 0) out[row] = v + bl[0];
}

// ---------------- launch ----------------
extern "C" void kernel_launch(void* const* d_in, const int* in_sizes, int n_in,
                              void* d_out, int out_size) {
    const float* x  = (const float*)d_in[0];
    const void*  ei = d_in[1];
    const float* ew = (const float*)d_in[2];
    const float* W1 = (const float*)d_in[3];
    const float* g1 = (const float*)d_in[5];
    const float* be1= (const float*)d_in[6];
    const float* W2 = (const float*)d_in[7];
    const float* g2 = (const float*)d_in[9];
    const float* be2= (const float*)d_in[10];
    const float* Wl = (const float*)d_in[11];
    const float* bl = (const float*)d_in[12];
    float* out = (float*)d_out;

    int n = in_sizes[0] / FIN;   // 100000
    int e = in_sizes[2];         // 1600000
    float invn = 1.0f / (float)n;

    int tb = 256;
    int gE   = (e + tb - 1) / tb;
    int gB   = (n + 255) / 256;                     // gemm role blocks
    int HB   = 592;                                 // hist role blocks
    int gG2  = (n + 511) / 512;                     // gemm2: 256 thr, 512 rows/blk
    int gF   = (int)(((long)n * 8 + tb - 1) / tb);  // 8 lanes per row
    int nsb  = (n + SCAN_B - 1) / SCAN_B;           // scan blocks (<=128)

    k_pre<<<gB + HB, 256>>>(x, W1, ei, ew, n, e, gB, HB);
    k_scanF<<<nsb, SCAN_B>>>(n, e);
    k_fill<<<gE, tb>>>(ei, ew, n, e);

    k_gather1<<<1024, tb>>>(n);

    k_gemm2<<<gG2, tb>>>(W2, g1, be1, n, invn);
    k_gather2<<<1024, tb>>>(n);

    k_final<<<gF, tb>>>(Wl, bl, g2, be2, out, n, invn);
}